// round 11
// baseline (speedup 1.0000x reference)
#include <cuda_runtime.h>
#include <cuda_bf16.h>
#include <math.h>
#include <cstdint>

#define IN_DIM 512
#define HID    256
#define LAT    128
#define F2     256
#define NNODE  8192
#define NEDGE  262144
#define NCHUNK 32          // edges per chunk = 8192 -> chunk = e >> 13

typedef __nv_bfloat16 bf16;

// ---------------- scratch ----------------
__device__ float g_buf1[NNODE * 256];
__device__ float g_buf3[NNODE * 256];
__device__ float g_dinv[NNODE];
__device__ int   g_cnt [NNODE];
__device__ int   g_rowp[NNODE + 1];
__device__ int   g_priv[NNODE * NCHUNK];  // [node][chunk]
__device__ int   g_col [NEDGE];
__device__ bf16  g_hh[NNODE * HID];
__device__ bf16  g_hl[NNODE * HID];
__device__ bf16  g_zh[NNODE * LAT];
__device__ bf16  g_zl[NNODE * LAT];
__device__ bf16  g_w1t_h[256 * 512];
__device__ bf16  g_w1t_l[256 * 512];
__device__ bf16  g_w23t_h[256 * 256];
__device__ bf16  g_w23t_l[256 * 256];

// ---------------- side stream / events ----------------
struct SideInit {
    cudaStream_t side;
    cudaEvent_t evFork, evJoin;
    SideInit() {
        cudaStreamCreateWithFlags(&side, cudaStreamNonBlocking);
        cudaEventCreateWithFlags(&evFork, cudaEventDisableTiming);
        cudaEventCreateWithFlags(&evJoin, cudaEventDisableTiming);
    }
};
static SideInit g_side;

// ---------------- helpers ----------------
__device__ __forceinline__ void split2(float v, bf16 &h, bf16 &l) {
    h = __float2bfloat16(v);
    l = __float2bfloat16(v - __bfloat162float(h));
}
__device__ __forceinline__ uint32_t pkbf(bf16 a, bf16 b) {
    return (uint32_t)__bfloat16_as_ushort(a) | ((uint32_t)__bfloat16_as_ushort(b) << 16);
}
__device__ __forceinline__ void mma_bf16(float *d, const uint32_t *a,
                                         uint32_t b0, uint32_t b1) {
    asm volatile(
        "mma.sync.aligned.m16n8k16.row.col.f32.bf16.bf16.f32 "
        "{%0,%1,%2,%3}, {%4,%5,%6,%7}, {%8,%9}, {%0,%1,%2,%3};"
        : "+f"(d[0]), "+f"(d[1]), "+f"(d[2]), "+f"(d[3])
        : "r"(a[0]), "r"(a[1]), "r"(a[2]), "r"(a[3]), "r"(b0), "r"(b1));
}

// ---------------- CSR build (privatized [node][chunk], warp-per-node scan) ----
__global__ void k_hist_priv(int *priv, const int *__restrict__ dst, int E) {
    int e = blockIdx.x * 256 + threadIdx.x;
    if (e < E) atomicAdd(&priv[dst[e] * NCHUNK + (e >> 13)], 1);
}
__global__ void k_sum(const int *__restrict__ priv, int *cnt, int n) {
    int warp = (blockIdx.x * blockDim.x + threadIdx.x) >> 5;
    int lane = threadIdx.x & 31;
    if (warp >= n) return;
    int v = priv[warp * NCHUNK + lane];
#pragma unroll
    for (int o = 16; o; o >>= 1) v += __shfl_xor_sync(0xffffffffu, v, o);
    if (lane == 0) cnt[warp] = v;
}
__global__ void k_scan(const int *__restrict__ cnt, int *rowp, float *dinv) {
    __shared__ int sm[1024];
    int t = threadIdx.x;
    int loc[8]; int s = 0;
#pragma unroll
    for (int j = 0; j < 8; j++) { loc[j] = s; s += cnt[t * 8 + j]; }
    sm[t] = s;
    __syncthreads();
    int v = s;
    for (int off = 1; off < 1024; off <<= 1) {
        int add = (t >= off) ? sm[t - off] : 0;
        __syncthreads();
        v += add; sm[t] = v;
        __syncthreads();
    }
    int exc = v - s;
#pragma unroll
    for (int j = 0; j < 8; j++) {
        rowp[t * 8 + j] = exc + loc[j];
        dinv[t * 8 + j] = rsqrtf((float)cnt[t * 8 + j] + 1.0f);
    }
    if (t == 1023) rowp[NNODE] = v;
}
__global__ void k_offsets(int *priv, const int *__restrict__ rowp, int n) {
    int warp = (blockIdx.x * blockDim.x + threadIdx.x) >> 5;
    int lane = threadIdx.x & 31;
    if (warp >= n) return;
    int v = priv[warp * NCHUNK + lane];
    int s = v;
#pragma unroll
    for (int o = 1; o < 32; o <<= 1) {
        int t = __shfl_up_sync(0xffffffffu, s, o);
        if (lane >= o) s += t;
    }
    priv[warp * NCHUNK + lane] = rowp[warp] + s - v;
}
__global__ void k_fill_priv(int *priv, int *col, const int *__restrict__ src,
                            const int *__restrict__ dst, int E) {
    int e = blockIdx.x * 256 + threadIdx.x;
    if (e >= E) return;
    int slot = atomicAdd(&priv[dst[e] * NCHUNK + (e >> 13)], 1);
    col[slot] = src[e];
}

// ---------------- weight conversions ----------------
__global__ void k_convert_w(const float *__restrict__ W1, const float *__restrict__ Wmu,
                            const float *__restrict__ Wls,
                            bf16 *__restrict__ w1h, bf16 *__restrict__ w1l,
                            bf16 *__restrict__ w23h, bf16 *__restrict__ w23l) {
    int t = blockIdx.x * 256 + threadIdx.x;
    if (t < IN_DIM * HID) {
        int k = t >> 8, c = t & 255;
        bf16 h, l;
        split2(W1[t], h, l);
        w1h[c * IN_DIM + k] = h;
        w1l[c * IN_DIM + k] = l;
        return;
    }
    t -= IN_DIM * HID;
    if (t < F2 * HID) {
        int nn = t >> 8, k = t & 255;
        float v = (nn < LAT) ? Wmu[k * LAT + nn] : Wls[k * LAT + (nn - LAT)];
        bf16 h, l;
        split2(v, h, l);
        w23h[t] = h; w23l[t] = l;
    }
}

// ---------------- bf16-split HMMA GEMM: C[M,N] = A[M,K] @ B[N,K]^T ------------
// Tile 128(m) x 64(n), BK=64; 8 warps each 32m x 32n; 2-3 CTAs/SM for overlap.
#define GS 72
#define GTILE_A (128 * GS)
#define GTILE_B (64 * GS)
#define GSMEM ((2 * GTILE_A + 2 * GTILE_B) * 2)

template <int SPLITA>
__global__ __launch_bounds__(256, 2)
void k_gemm_bs(const void *__restrict__ Aq, const bf16 *__restrict__ Albf,
               const bf16 *__restrict__ Bh, const bf16 *__restrict__ Bl,
               float *__restrict__ C, int M, int N, int K) {
    extern __shared__ char smem[];
    bf16 *sAh = (bf16 *)smem;
    bf16 *sAl = sAh + GTILE_A;
    bf16 *sBh = sAl + GTILE_A;
    bf16 *sBl = sBh + GTILE_B;
    const int tid = threadIdx.x;
    const int wid = tid >> 5, lane = tid & 31;
    const int bm = blockIdx.y * 128, bn = blockIdx.x * 64;
    const int wm = (wid & 3) * 32, wn = (wid >> 2) * 32;
    const int tq = lane >> 2, tr = lane & 3;

    float c[2][4][4];
#pragma unroll
    for (int mf = 0; mf < 2; mf++)
#pragma unroll
        for (int nf = 0; nf < 4; nf++)
#pragma unroll
            for (int r = 0; r < 4; r++) c[mf][nf][r] = 0.0f;

    for (int kc = 0; kc < K; kc += 64) {
        // A tile: 128 rows x 64 k (1024 uint4 groups per hi/lo)
#pragma unroll
        for (int it = 0; it < 4; it++) {
            int idx = tid + it * 256;
            int r = idx >> 3, g = idx & 7;
            int doff = r * GS + g * 8;
            if (SPLITA) {
                const float *ap = (const float *)Aq + (size_t)(bm + r) * K + kc + g * 8;
                float4 v0 = *(const float4 *)ap;
                float4 v1 = *(const float4 *)(ap + 4);
                bf16 h[8], l[8];
                split2(v0.x, h[0], l[0]); split2(v0.y, h[1], l[1]);
                split2(v0.z, h[2], l[2]); split2(v0.w, h[3], l[3]);
                split2(v1.x, h[4], l[4]); split2(v1.y, h[5], l[5]);
                split2(v1.z, h[6], l[6]); split2(v1.w, h[7], l[7]);
                *(uint4 *)(sAh + doff) = make_uint4(pkbf(h[0], h[1]), pkbf(h[2], h[3]),
                                                    pkbf(h[4], h[5]), pkbf(h[6], h[7]));
                *(uint4 *)(sAl + doff) = make_uint4(pkbf(l[0], l[1]), pkbf(l[2], l[3]),
                                                    pkbf(l[4], l[5]), pkbf(l[6], l[7]));
            } else {
                size_t aoff = (size_t)(bm + r) * K + kc + g * 8;
                *(uint4 *)(sAh + doff) = *(const uint4 *)((const bf16 *)Aq + aoff);
                *(uint4 *)(sAl + doff) = *(const uint4 *)(Albf + aoff);
            }
        }
        // B tile: 64 rows x 64 k (512 uint4 groups per hi/lo)
#pragma unroll
        for (int it = 0; it < 2; it++) {
            int idx = tid + it * 256;
            int r = idx >> 3, g = idx & 7;
            int doff = r * GS + g * 8;
            size_t boff = (size_t)(bn + r) * K + kc + g * 8;
            *(uint4 *)(sBh + doff) = *(const uint4 *)(Bh + boff);
            *(uint4 *)(sBl + doff) = *(const uint4 *)(Bl + boff);
        }
        __syncthreads();
#pragma unroll
        for (int ks = 0; ks < 4; ks++) {
            int k0 = ks * 16;
            uint32_t ah[2][4], al[2][4];
#pragma unroll
            for (int mf = 0; mf < 2; mf++) {
                int base = (wm + mf * 16 + tq) * GS + k0 + tr * 2;
                ah[mf][0] = *(const uint32_t *)(sAh + base);
                ah[mf][1] = *(const uint32_t *)(sAh + base + 8 * GS);
                ah[mf][2] = *(const uint32_t *)(sAh + base + 8);
                ah[mf][3] = *(const uint32_t *)(sAh + base + 8 * GS + 8);
                al[mf][0] = *(const uint32_t *)(sAl + base);
                al[mf][1] = *(const uint32_t *)(sAl + base + 8 * GS);
                al[mf][2] = *(const uint32_t *)(sAl + base + 8);
                al[mf][3] = *(const uint32_t *)(sAl + base + 8 * GS + 8);
            }
#pragma unroll
            for (int nf = 0; nf < 4; nf++) {
                int bbase = (wn + nf * 8 + tq) * GS + k0 + tr * 2;
                uint32_t bh0 = *(const uint32_t *)(sBh + bbase);
                uint32_t bh1 = *(const uint32_t *)(sBh + bbase + 8);
                uint32_t bl0 = *(const uint32_t *)(sBl + bbase);
                uint32_t bl1 = *(const uint32_t *)(sBl + bbase + 8);
#pragma unroll
                for (int mf = 0; mf < 2; mf++) {
                    mma_bf16(c[mf][nf], ah[mf], bh0, bh1);
                    mma_bf16(c[mf][nf], ah[mf], bl0, bl1);
                    mma_bf16(c[mf][nf], al[mf], bh0, bh1);
                }
            }
        }
        __syncthreads();
    }
#pragma unroll
    for (int mf = 0; mf < 2; mf++)
#pragma unroll
        for (int half = 0; half < 2; half++) {
            int row = bm + wm + mf * 16 + tq + half * 8;
            float *rp = C + (size_t)row * N + bn + wn + tr * 2;
#pragma unroll
            for (int nf = 0; nf < 4; nf++)
                *(float2 *)(rp + nf * 8) =
                    make_float2(c[mf][nf][2 * half], c[mf][nf][2 * half + 1]);
        }
}

// ---------------- gather layer 1 ----------------
__global__ void k_gather1(const float *__restrict__ pre, bf16 *__restrict__ hh,
                          bf16 *__restrict__ hl, const int *__restrict__ rowp,
                          const int *__restrict__ col, const float *__restrict__ dinv,
                          const float *__restrict__ bias, int n) {
    int warp = (blockIdx.x * blockDim.x + threadIdx.x) >> 5;
    int lane = threadIdx.x & 31;
    if (warp >= n) return;
    const float4 *p4 = (const float4 *)pre;
    float dn = dinv[warp];
    float nn = dn * dn;
    float4 a0 = p4[(size_t)warp * 64 + lane];
    float4 a1 = p4[(size_t)warp * 64 + 32 + lane];
    a0.x *= nn; a0.y *= nn; a0.z *= nn; a0.w *= nn;
    a1.x *= nn; a1.y *= nn; a1.z *= nn; a1.w *= nn;

    int s0 = rowp[warp], s1 = rowp[warp + 1];
    for (int base = s0; base < s1; base += 32) {
        int m = s1 - base; if (m > 32) m = 32;
        int srcv = 0; float nrmv = 0.0f;
        if (lane < m) { srcv = col[base + lane]; nrmv = dinv[srcv] * dn; }
        for (int j = 0; j < m; j++) {
            int s = __shfl_sync(0xffffffffu, srcv, j);
            float w = __shfl_sync(0xffffffffu, nrmv, j);
            float4 v0 = p4[(size_t)s * 64 + lane];
            float4 v1 = p4[(size_t)s * 64 + 32 + lane];
            a0.x += v0.x * w; a0.y += v0.y * w; a0.z += v0.z * w; a0.w += v0.w * w;
            a1.x += v1.x * w; a1.y += v1.y * w; a1.z += v1.z * w; a1.w += v1.w * w;
        }
    }
    float4 b0 = *(const float4 *)(bias + lane * 4);
    float4 b1 = *(const float4 *)(bias + 128 + lane * 4);
    float f[8];
    f[0] = fmaxf(a0.x + b0.x, 0.f); f[1] = fmaxf(a0.y + b0.y, 0.f);
    f[2] = fmaxf(a0.z + b0.z, 0.f); f[3] = fmaxf(a0.w + b0.w, 0.f);
    f[4] = fmaxf(a1.x + b1.x, 0.f); f[5] = fmaxf(a1.y + b1.y, 0.f);
    f[6] = fmaxf(a1.z + b1.z, 0.f); f[7] = fmaxf(a1.w + b1.w, 0.f);
    bf16 h[8], l[8];
#pragma unroll
    for (int j = 0; j < 8; j++) split2(f[j], h[j], l[j]);
    uint2 *hh2 = (uint2 *)hh, *hl2 = (uint2 *)hl;
    hh2[(size_t)warp * 64 + lane]      = make_uint2(pkbf(h[0], h[1]), pkbf(h[2], h[3]));
    hh2[(size_t)warp * 64 + 32 + lane] = make_uint2(pkbf(h[4], h[5]), pkbf(h[6], h[7]));
    hl2[(size_t)warp * 64 + lane]      = make_uint2(pkbf(l[0], l[1]), pkbf(l[2], l[3]));
    hl2[(size_t)warp * 64 + 32 + lane] = make_uint2(pkbf(l[4], l[5]), pkbf(l[6], l[7]));
}

// ---------------- gather layer 2 + reparametrize ----------------
__global__ void k_gather2(const float *__restrict__ pre, const int *__restrict__ rowp,
                          const int *__restrict__ col, const float *__restrict__ dinv,
                          const float *__restrict__ bmu, const float *__restrict__ bls,
                          const float *__restrict__ eps, bf16 *__restrict__ zh,
                          bf16 *__restrict__ zl, float *__restrict__ out,
                          int n, size_t mu_off, size_t ls_off) {
    int warp = (blockIdx.x * blockDim.x + threadIdx.x) >> 5;
    int lane = threadIdx.x & 31;
    if (warp >= n) return;
    const float4 *p4 = (const float4 *)pre;
    float dn = dinv[warp];
    float nn = dn * dn;
    float4 a0 = p4[(size_t)warp * 64 + lane];
    float4 a1 = p4[(size_t)warp * 64 + 32 + lane];
    a0.x *= nn; a0.y *= nn; a0.z *= nn; a0.w *= nn;
    a1.x *= nn; a1.y *= nn; a1.z *= nn; a1.w *= nn;

    int s0 = rowp[warp], s1 = rowp[warp + 1];
    for (int base = s0; base < s1; base += 32) {
        int m = s1 - base; if (m > 32) m = 32;
        int srcv = 0; float nrmv = 0.0f;
        if (lane < m) { srcv = col[base + lane]; nrmv = dinv[srcv] * dn; }
        for (int j = 0; j < m; j++) {
            int s = __shfl_sync(0xffffffffu, srcv, j);
            float w = __shfl_sync(0xffffffffu, nrmv, j);
            float4 v0 = p4[(size_t)s * 64 + lane];
            float4 v1 = p4[(size_t)s * 64 + 32 + lane];
            a0.x += v0.x * w; a0.y += v0.y * w; a0.z += v0.z * w; a0.w += v0.w * w;
            a1.x += v1.x * w; a1.y += v1.y * w; a1.z += v1.z * w; a1.w += v1.w * w;
        }
    }
    float4 bm4 = *(const float4 *)(bmu + lane * 4);
    float4 bl4 = *(const float4 *)(bls + lane * 4);
    float4 mu = make_float4(a0.x + bm4.x, a0.y + bm4.y, a0.z + bm4.z, a0.w + bm4.w);
    float4 ls = make_float4(a1.x + bl4.x, a1.y + bl4.y, a1.z + bl4.z, a1.w + bl4.w);
    float4 ep = ((const float4 *)eps)[(size_t)warp * 32 + lane];
    float z0 = ep.x * __expf(ls.x) + mu.x;
    float z1 = ep.y * __expf(ls.y) + mu.y;
    float z2 = ep.z * __expf(ls.z) + mu.z;
    float z3 = ep.w * __expf(ls.w) + mu.w;
    bf16 h0, h1, h2, h3, l0, l1, l2, l3;
    split2(z0, h0, l0); split2(z1, h1, l1);
    split2(z2, h2, l2); split2(z3, h3, l3);
    ((uint2 *)zh)[(size_t)warp * 32 + lane] = make_uint2(pkbf(h0, h1), pkbf(h2, h3));
    ((uint2 *)zl)[(size_t)warp * 32 + lane] = make_uint2(pkbf(l0, l1), pkbf(l2, l3));
    ((float4 *)(out + mu_off))[(size_t)warp * 32 + lane] = mu;
    ((float4 *)(out + ls_off))[(size_t)warp * 32 + lane] = ls;
}

// ---------------- adj = sigmoid(Z Z^T), HMMA bf16-split, 3-tile 2-phase -------
#define ZSTRIDE 136
#define ZTILE   (128 * ZSTRIDE)
#define ZT_SMEM (3 * ZTILE * 2)

__global__ __launch_bounds__(256, 2)
void k_zzt_mma(const bf16 *__restrict__ zh, const bf16 *__restrict__ zl,
               float *__restrict__ out, int n) {
    extern __shared__ char smem[];
    bf16 *tiles = (bf16 *)smem;

    int i = blockIdx.x;
    int bx = (int)((sqrtf(8.0f * (float)i + 1.0f) - 1.0f) * 0.5f);
    while ((bx + 1) * (bx + 2) / 2 <= i) bx++;
    while (bx * (bx + 1) / 2 > i) bx--;
    int by = i - bx * (bx + 1) / 2;
    const int bm = by * 128, bn = bx * 128;

    const int tid = threadIdx.x;
    const int wid = tid >> 5, lane = tid & 31;
    const int wm = (wid & 3) * 32, wn = (wid >> 2) * 64;
    const int tq = lane >> 2, tr = lane & 3;

    bf16 *Ah = tiles, *Bh = tiles + ZTILE, *T2 = tiles + 2 * ZTILE;

#pragma unroll
    for (int tile = 0; tile < 3; tile++) {
        const bf16 *src = (tile == 2) ? zl : zh;
        int rowoff = (tile == 0) ? bm : bn;
        bf16 *dstt = tiles + tile * ZTILE;
#pragma unroll
        for (int it = 0; it < 8; it++) {
            int idx = tid + it * 256;
            int r = idx >> 4, g = idx & 15;
            uint4 v = *(const uint4 *)(src + (size_t)(rowoff + r) * 128 + g * 8);
            *(uint4 *)(dstt + r * ZSTRIDE + g * 8) = v;
        }
    }
    __syncthreads();

    float c[2][8][4];
#pragma unroll
    for (int mf = 0; mf < 2; mf++)
#pragma unroll
        for (int nf = 0; nf < 8; nf++)
#pragma unroll
            for (int r = 0; r < 4; r++) c[mf][nf][r] = 0.0f;

    // phase 1: acc += Ah*Bh^T + Ah*Bl^T
#pragma unroll
    for (int ks = 0; ks < 8; ks++) {
        int k0 = ks * 16;
        uint32_t ah[2][4];
#pragma unroll
        for (int mf = 0; mf < 2; mf++) {
            int base = (wm + mf * 16 + tq) * ZSTRIDE + k0 + tr * 2;
            ah[mf][0] = *(const uint32_t *)(Ah + base);
            ah[mf][1] = *(const uint32_t *)(Ah + base + 8 * ZSTRIDE);
            ah[mf][2] = *(const uint32_t *)(Ah + base + 8);
            ah[mf][3] = *(const uint32_t *)(Ah + base + 8 * ZSTRIDE + 8);
        }
#pragma unroll
        for (int nf = 0; nf < 8; nf++) {
            int bbase = (wn + nf * 8 + tq) * ZSTRIDE + k0 + tr * 2;
            uint32_t bh0 = *(const uint32_t *)(Bh + bbase);
            uint32_t bh1 = *(const uint32_t *)(Bh + bbase + 8);
            uint32_t bl0 = *(const uint32_t *)(T2 + bbase);
            uint32_t bl1 = *(const uint32_t *)(T2 + bbase + 8);
#pragma unroll
            for (int mf = 0; mf < 2; mf++) {
                mma_bf16(c[mf][nf], ah[mf], bh0, bh1);
                mma_bf16(c[mf][nf], ah[mf], bl0, bl1);
            }
        }
    }

    // reload T2 = Al(bm, zl)
    __syncthreads();
#pragma unroll
    for (int it = 0; it < 8; it++) {
        int idx = tid + it * 256;
        int r = idx >> 4, g = idx & 15;
        uint4 v = *(const uint4 *)(zl + (size_t)(bm + r) * 128 + g * 8);
        *(uint4 *)(T2 + r * ZSTRIDE + g * 8) = v;
    }
    __syncthreads();

    // phase 2: acc += Al*Bh^T
#pragma unroll
    for (int ks = 0; ks < 8; ks++) {
        int k0 = ks * 16;
        uint32_t al[2][4];
#pragma unroll
        for (int mf = 0; mf < 2; mf++) {
            int base = (wm + mf * 16 + tq) * ZSTRIDE + k0 + tr * 2;
            al[mf][0] = *(const uint32_t *)(T2 + base);
            al[mf][1] = *(const uint32_t *)(T2 + base + 8 * ZSTRIDE);
            al[mf][2] = *(const uint32_t *)(T2 + base + 8);
            al[mf][3] = *(const uint32_t *)(T2 + base + 8 * ZSTRIDE + 8);
        }
#pragma unroll
        for (int nf = 0; nf < 8; nf++) {
            int bbase = (wn + nf * 8 + tq) * ZSTRIDE + k0 + tr * 2;
            uint32_t bh0 = *(const uint32_t *)(Bh + bbase);
            uint32_t bh1 = *(const uint32_t *)(Bh + bbase + 8);
#pragma unroll
            for (int mf = 0; mf < 2; mf++)
                mma_bf16(c[mf][nf], al[mf], bh0, bh1);
        }
    }

#pragma unroll
    for (int mf = 0; mf < 2; mf++)
#pragma unroll
        for (int nf = 0; nf < 8; nf++)
#pragma unroll
            for (int r = 0; r < 4; r++)
                c[mf][nf][r] = __fdividef(1.0f, 1.0f + __expf(-c[mf][nf][r]));

#pragma unroll
    for (int mf = 0; mf < 2; mf++)
#pragma unroll
        for (int half = 0; half < 2; half++) {
            int row = bm + wm + mf * 16 + tq + half * 8;
            float *rp = out + (size_t)row * n + bn + wn + tr * 2;
#pragma unroll
            for (int nf = 0; nf < 8; nf++)
                *(float2 *)(rp + nf * 8) =
                    make_float2(c[mf][nf][2 * half], c[mf][nf][2 * half + 1]);
        }

    if (bx == by) return;

    __syncthreads();
    float *sT = (float *)smem;
#pragma unroll
    for (int mf = 0; mf < 2; mf++)
#pragma unroll
        for (int nf = 0; nf < 8; nf++) {
            int colc = wn + nf * 8 + tr * 2;
            int row0 = wm + mf * 16 + tq;
            sT[(colc + 0) * 132 + row0]     = c[mf][nf][0];
            sT[(colc + 1) * 132 + row0]     = c[mf][nf][1];
            sT[(colc + 0) * 132 + row0 + 8] = c[mf][nf][2];
            sT[(colc + 1) * 132 + row0 + 8] = c[mf][nf][3];
        }
    __syncthreads();
#pragma unroll
    for (int it = 0; it < 16; it++) {
        int idx = tid + it * 256;
        int mr = idx >> 5, mc4 = idx & 31;
        float4 v = *(const float4 *)&sT[mr * 132 + mc4 * 4];
        *(float4 *)(out + (size_t)(bn + mr) * n + bm + mc4 * 4) = v;
    }
}

// ---------------- launcher ----------------
extern "C" void kernel_launch(void *const *d_in, const int *in_sizes, int n_in,
                              void *d_out, int out_size) {
    const float *x   = (const float *)d_in[0];
    const int *ei    = (const int *)d_in[1];
    const float *eps = (const float *)d_in[2];
    const float *W1  = (const float *)d_in[3];
    const float *b1  = (const float *)d_in[4];
    const float *Wmu = (const float *)d_in[5];
    const float *bmu = (const float *)d_in[6];
    const float *Wls = (const float *)d_in[7];
    const float *bls = (const float *)d_in[8];
    float *out       = (float *)d_out;

    const int n = in_sizes[0] / IN_DIM;   // 8192
    const int E = in_sizes[1] / 2;        // 262144
    const int *src = ei;
    const int *dst = ei + E;

    float *buf1, *buf3, *dinv;
    bf16 *hh, *hl, *zh, *zl, *w1h, *w1l, *w23h, *w23l;
    int *cnt, *rowp, *priv, *col;
    cudaGetSymbolAddress((void **)&buf1, g_buf1);
    cudaGetSymbolAddress((void **)&buf3, g_buf3);
    cudaGetSymbolAddress((void **)&dinv, g_dinv);
    cudaGetSymbolAddress((void **)&cnt,  g_cnt);
    cudaGetSymbolAddress((void **)&rowp, g_rowp);
    cudaGetSymbolAddress((void **)&priv, g_priv);
    cudaGetSymbolAddress((void **)&col,  g_col);
    cudaGetSymbolAddress((void **)&hh,   g_hh);
    cudaGetSymbolAddress((void **)&hl,   g_hl);
    cudaGetSymbolAddress((void **)&zh,   g_zh);
    cudaGetSymbolAddress((void **)&zl,   g_zl);
    cudaGetSymbolAddress((void **)&w1h,  g_w1t_h);
    cudaGetSymbolAddress((void **)&w1l,  g_w1t_l);
    cudaGetSymbolAddress((void **)&w23h, g_w23t_h);
    cudaGetSymbolAddress((void **)&w23l, g_w23t_l);

    static int smem_set = 0;
    if (!smem_set) {
        cudaFuncSetAttribute(k_zzt_mma, cudaFuncAttributeMaxDynamicSharedMemorySize,
                             ZT_SMEM);
        cudaFuncSetAttribute(k_gemm_bs<0>, cudaFuncAttributeMaxDynamicSharedMemorySize,
                             GSMEM);
        cudaFuncSetAttribute(k_gemm_bs<1>, cudaFuncAttributeMaxDynamicSharedMemorySize,
                             GSMEM);
        smem_set = 1;
    }

    const size_t mu_off = (size_t)n * n;
    const size_t ls_off = mu_off + (size_t)n * LAT;

    // ---- fork: CSR build on side stream ----
    cudaEventRecord(g_side.evFork, 0);
    cudaStreamWaitEvent(g_side.side, g_side.evFork, 0);

    cudaMemsetAsync(priv, 0, NNODE * NCHUNK * sizeof(int), g_side.side);
    k_hist_priv<<<(E + 255) / 256, 256, 0, g_side.side>>>(priv, dst, E);
    k_sum<<<(n * 32 + 255) / 256, 256, 0, g_side.side>>>(priv, cnt, n);
    k_scan<<<1, 1024, 0, g_side.side>>>(cnt, rowp, dinv);
    k_offsets<<<(n * 32 + 255) / 256, 256, 0, g_side.side>>>(priv, rowp, n);
    k_fill_priv<<<(E + 255) / 256, 256, 0, g_side.side>>>(priv, col, src, dst, E);
    cudaEventRecord(g_side.evJoin, g_side.side);

    // ---- main stream: weight conversion + GEMM1 (x split fused in-kernel) ----
    int wthreads = IN_DIM * HID + F2 * HID;
    k_convert_w<<<(wthreads + 255) / 256, 256>>>(W1, Wmu, Wls, w1h, w1l, w23h, w23l);
    k_gemm_bs<1><<<dim3(HID / 64, n / 128), 256, GSMEM>>>(x, nullptr, w1h, w1l,
                                                          buf1, n, HID, IN_DIM);

    // ---- join: gathers need CSR ----
    cudaStreamWaitEvent(0, g_side.evJoin, 0);

    k_gather1<<<(n * 32 + 255) / 256, 256>>>(buf1, hh, hl, rowp, col, dinv, b1, n);
    k_gemm_bs<0><<<dim3(F2 / 64, n / 128), 256, GSMEM>>>(hh, hl, w23h, w23l, buf3,
                                                         n, F2, HID);
    k_gather2<<<(n * 32 + 255) / 256, 256>>>(buf3, rowp, col, dinv, bmu, bls, eps,
                                             zh, zl, out, n, mu_off, ls_off);

    int nt = (n / 128) * (n / 128 + 1) / 2;   // 2080
    k_zzt_mma<<<nt, 256, ZT_SMEM>>>(zh, zl, out, n);
}

// round 12
// speedup vs baseline: 1.0113x; 1.0113x over previous
#include <cuda_runtime.h>
#include <cuda_bf16.h>
#include <math.h>
#include <cstdint>

#define IN_DIM 512
#define HID    256
#define LAT    128
#define F2     256
#define NNODE  8192
#define NEDGE  262144
#define NCHUNK 32          // edges per chunk = 8192 -> chunk = e >> 13

typedef __nv_bfloat16 bf16;

// ---------------- scratch ----------------
__device__ float g_buf1[NNODE * 256];
__device__ float g_buf3[NNODE * 256];
__device__ float g_dinv[NNODE];
__device__ int   g_cnt [NNODE];
__device__ int   g_rowp[NNODE + 1];
__device__ int   g_priv[NNODE * NCHUNK];  // [node][chunk]
__device__ int   g_col [NEDGE];
__device__ bf16  g_hh[NNODE * HID];
__device__ bf16  g_hl[NNODE * HID];
__device__ bf16  g_zh[NNODE * LAT];
__device__ bf16  g_zl[NNODE * LAT];
__device__ bf16  g_w1t_h[256 * 512];
__device__ bf16  g_w1t_l[256 * 512];
__device__ bf16  g_w23t_h[256 * 256];
__device__ bf16  g_w23t_l[256 * 256];

// ---------------- side stream / events ----------------
struct SideInit {
    cudaStream_t side;
    cudaEvent_t evFork, evJoin;
    SideInit() {
        cudaStreamCreateWithFlags(&side, cudaStreamNonBlocking);
        cudaEventCreateWithFlags(&evFork, cudaEventDisableTiming);
        cudaEventCreateWithFlags(&evJoin, cudaEventDisableTiming);
    }
};
static SideInit g_side;

// ---------------- helpers ----------------
__device__ __forceinline__ void split2(float v, bf16 &h, bf16 &l) {
    h = __float2bfloat16(v);
    l = __float2bfloat16(v - __bfloat162float(h));
}
__device__ __forceinline__ uint32_t pkbf(bf16 a, bf16 b) {
    return (uint32_t)__bfloat16_as_ushort(a) | ((uint32_t)__bfloat16_as_ushort(b) << 16);
}
__device__ __forceinline__ float fast_sigmoid(float x) {
    float t;
    asm("tanh.approx.f32 %0, %1;" : "=f"(t) : "f"(x * 0.5f));
    return fmaf(0.5f, t, 0.5f);
}
__device__ __forceinline__ void mma_bf16(float *d, const uint32_t *a,
                                         uint32_t b0, uint32_t b1) {
    asm volatile(
        "mma.sync.aligned.m16n8k16.row.col.f32.bf16.bf16.f32 "
        "{%0,%1,%2,%3}, {%4,%5,%6,%7}, {%8,%9}, {%0,%1,%2,%3};"
        : "+f"(d[0]), "+f"(d[1]), "+f"(d[2]), "+f"(d[3])
        : "r"(a[0]), "r"(a[1]), "r"(a[2]), "r"(a[3]), "r"(b0), "r"(b1));
}

// ---------------- CSR build (privatized [node][chunk], warp-per-node scan) ----
__global__ void k_hist_priv(int *priv, const int *__restrict__ dst, int E) {
    int e = blockIdx.x * 256 + threadIdx.x;
    if (e < E) atomicAdd(&priv[dst[e] * NCHUNK + (e >> 13)], 1);
}
__global__ void k_sum(const int *__restrict__ priv, int *cnt, int n) {
    int warp = (blockIdx.x * blockDim.x + threadIdx.x) >> 5;
    int lane = threadIdx.x & 31;
    if (warp >= n) return;
    int v = priv[warp * NCHUNK + lane];
#pragma unroll
    for (int o = 16; o; o >>= 1) v += __shfl_xor_sync(0xffffffffu, v, o);
    if (lane == 0) cnt[warp] = v;
}
__global__ void k_scan(const int *__restrict__ cnt, int *rowp, float *dinv) {
    __shared__ int sm[1024];
    int t = threadIdx.x;
    int loc[8]; int s = 0;
#pragma unroll
    for (int j = 0; j < 8; j++) { loc[j] = s; s += cnt[t * 8 + j]; }
    sm[t] = s;
    __syncthreads();
    int v = s;
    for (int off = 1; off < 1024; off <<= 1) {
        int add = (t >= off) ? sm[t - off] : 0;
        __syncthreads();
        v += add; sm[t] = v;
        __syncthreads();
    }
    int exc = v - s;
#pragma unroll
    for (int j = 0; j < 8; j++) {
        rowp[t * 8 + j] = exc + loc[j];
        dinv[t * 8 + j] = rsqrtf((float)cnt[t * 8 + j] + 1.0f);
    }
    if (t == 1023) rowp[NNODE] = v;
}
__global__ void k_offsets(int *priv, const int *__restrict__ rowp, int n) {
    int warp = (blockIdx.x * blockDim.x + threadIdx.x) >> 5;
    int lane = threadIdx.x & 31;
    if (warp >= n) return;
    int v = priv[warp * NCHUNK + lane];
    int s = v;
#pragma unroll
    for (int o = 1; o < 32; o <<= 1) {
        int t = __shfl_up_sync(0xffffffffu, s, o);
        if (lane >= o) s += t;
    }
    priv[warp * NCHUNK + lane] = rowp[warp] + s - v;
}
__global__ void k_fill_priv(int *priv, int *col, const int *__restrict__ src,
                            const int *__restrict__ dst, int E) {
    int e = blockIdx.x * 256 + threadIdx.x;
    if (e >= E) return;
    int slot = atomicAdd(&priv[dst[e] * NCHUNK + (e >> 13)], 1);
    col[slot] = src[e];
}

// ---------------- weight conversions ----------------
__global__ void k_convert_w(const float *__restrict__ W1, const float *__restrict__ Wmu,
                            const float *__restrict__ Wls,
                            bf16 *__restrict__ w1h, bf16 *__restrict__ w1l,
                            bf16 *__restrict__ w23h, bf16 *__restrict__ w23l) {
    int t = blockIdx.x * 256 + threadIdx.x;
    if (t < IN_DIM * HID) {
        int k = t >> 8, c = t & 255;
        bf16 h, l;
        split2(W1[t], h, l);
        w1h[c * IN_DIM + k] = h;
        w1l[c * IN_DIM + k] = l;
        return;
    }
    t -= IN_DIM * HID;
    if (t < F2 * HID) {
        int nn = t >> 8, k = t & 255;
        float v = (nn < LAT) ? Wmu[k * LAT + nn] : Wls[k * LAT + (nn - LAT)];
        bf16 h, l;
        split2(v, h, l);
        w23h[t] = h; w23l[t] = l;
    }
}

// ---------------- bf16-split HMMA GEMM: C[M,N] = A[M,K] @ B[N,K]^T ------------
// Tile 128x128, 8 warps (4m x 2n), BK=64.  (R10 proven config)
#define GS 72
#define GTILE (128 * GS)
#define GSMEM (4 * GTILE * 2)

template <int SPLITA>
__global__ __launch_bounds__(256, 1)
void k_gemm_bs(const void *__restrict__ Aq, const bf16 *__restrict__ Albf,
               const bf16 *__restrict__ Bh, const bf16 *__restrict__ Bl,
               float *__restrict__ C, int M, int N, int K) {
    extern __shared__ char smem[];
    bf16 *sAh = (bf16 *)smem;
    bf16 *sAl = sAh + GTILE;
    bf16 *sBh = sAl + GTILE;
    bf16 *sBl = sBh + GTILE;
    const int tid = threadIdx.x;
    const int wid = tid >> 5, lane = tid & 31;
    const int bm = blockIdx.y * 128, bn = blockIdx.x * 128;
    const int wm = (wid & 3) * 32, wn = (wid >> 2) * 64;
    const int tq = lane >> 2, tr = lane & 3;

    float c[2][8][4];
#pragma unroll
    for (int mf = 0; mf < 2; mf++)
#pragma unroll
        for (int nf = 0; nf < 8; nf++)
#pragma unroll
            for (int r = 0; r < 4; r++) c[mf][nf][r] = 0.0f;

    for (int kc = 0; kc < K; kc += 64) {
#pragma unroll
        for (int it = 0; it < 4; it++) {
            int idx = tid + it * 256;
            int r = idx >> 3, g = idx & 7;
            int doff = r * GS + g * 8;
            if (SPLITA) {
                const float *ap = (const float *)Aq + (size_t)(bm + r) * K + kc + g * 8;
                float4 v0 = *(const float4 *)ap;
                float4 v1 = *(const float4 *)(ap + 4);
                bf16 h[8], l[8];
                split2(v0.x, h[0], l[0]); split2(v0.y, h[1], l[1]);
                split2(v0.z, h[2], l[2]); split2(v0.w, h[3], l[3]);
                split2(v1.x, h[4], l[4]); split2(v1.y, h[5], l[5]);
                split2(v1.z, h[6], l[6]); split2(v1.w, h[7], l[7]);
                *(uint4 *)(sAh + doff) = make_uint4(pkbf(h[0], h[1]), pkbf(h[2], h[3]),
                                                    pkbf(h[4], h[5]), pkbf(h[6], h[7]));
                *(uint4 *)(sAl + doff) = make_uint4(pkbf(l[0], l[1]), pkbf(l[2], l[3]),
                                                    pkbf(l[4], l[5]), pkbf(l[6], l[7]));
            } else {
                size_t aoff = (size_t)(bm + r) * K + kc + g * 8;
                *(uint4 *)(sAh + doff) = *(const uint4 *)((const bf16 *)Aq + aoff);
                *(uint4 *)(sAl + doff) = *(const uint4 *)(Albf + aoff);
            }
            size_t boff = (size_t)(bn + r) * K + kc + g * 8;
            *(uint4 *)(sBh + doff) = *(const uint4 *)(Bh + boff);
            *(uint4 *)(sBl + doff) = *(const uint4 *)(Bl + boff);
        }
        __syncthreads();
#pragma unroll
        for (int ks = 0; ks < 4; ks++) {
            int k0 = ks * 16;
            uint32_t ah[2][4], al[2][4];
#pragma unroll
            for (int mf = 0; mf < 2; mf++) {
                int base = (wm + mf * 16 + tq) * GS + k0 + tr * 2;
                ah[mf][0] = *(const uint32_t *)(sAh + base);
                ah[mf][1] = *(const uint32_t *)(sAh + base + 8 * GS);
                ah[mf][2] = *(const uint32_t *)(sAh + base + 8);
                ah[mf][3] = *(const uint32_t *)(sAh + base + 8 * GS + 8);
                al[mf][0] = *(const uint32_t *)(sAl + base);
                al[mf][1] = *(const uint32_t *)(sAl + base + 8 * GS);
                al[mf][2] = *(const uint32_t *)(sAl + base + 8);
                al[mf][3] = *(const uint32_t *)(sAl + base + 8 * GS + 8);
            }
#pragma unroll
            for (int nf = 0; nf < 8; nf++) {
                int bbase = (wn + nf * 8 + tq) * GS + k0 + tr * 2;
                uint32_t bh0 = *(const uint32_t *)(sBh + bbase);
                uint32_t bh1 = *(const uint32_t *)(sBh + bbase + 8);
                uint32_t bl0 = *(const uint32_t *)(sBl + bbase);
                uint32_t bl1 = *(const uint32_t *)(sBl + bbase + 8);
#pragma unroll
                for (int mf = 0; mf < 2; mf++) {
                    mma_bf16(c[mf][nf], ah[mf], bh0, bh1);
                    mma_bf16(c[mf][nf], ah[mf], bl0, bl1);
                    mma_bf16(c[mf][nf], al[mf], bh0, bh1);
                }
            }
        }
        __syncthreads();
    }
#pragma unroll
    for (int mf = 0; mf < 2; mf++)
#pragma unroll
        for (int half = 0; half < 2; half++) {
            int row = bm + wm + mf * 16 + tq + half * 8;
            float *rp = C + (size_t)row * N + bn + wn + tr * 2;
#pragma unroll
            for (int nf = 0; nf < 8; nf++)
                *(float2 *)(rp + nf * 8) =
                    make_float2(c[mf][nf][2 * half], c[mf][nf][2 * half + 1]);
        }
}

// ---------------- gather layer 1 ----------------
__global__ void k_gather1(const float *__restrict__ pre, bf16 *__restrict__ hh,
                          bf16 *__restrict__ hl, const int *__restrict__ rowp,
                          const int *__restrict__ col, const float *__restrict__ dinv,
                          const float *__restrict__ bias, int n) {
    int warp = (blockIdx.x * blockDim.x + threadIdx.x) >> 5;
    int lane = threadIdx.x & 31;
    if (warp >= n) return;
    const float4 *p4 = (const float4 *)pre;
    float dn = dinv[warp];
    float nn = dn * dn;
    float4 a0 = p4[(size_t)warp * 64 + lane];
    float4 a1 = p4[(size_t)warp * 64 + 32 + lane];
    a0.x *= nn; a0.y *= nn; a0.z *= nn; a0.w *= nn;
    a1.x *= nn; a1.y *= nn; a1.z *= nn; a1.w *= nn;

    int s0 = rowp[warp], s1 = rowp[warp + 1];
    for (int base = s0; base < s1; base += 32) {
        int m = s1 - base; if (m > 32) m = 32;
        int srcv = 0; float nrmv = 0.0f;
        if (lane < m) { srcv = col[base + lane]; nrmv = dinv[srcv] * dn; }
        for (int j = 0; j < m; j++) {
            int s = __shfl_sync(0xffffffffu, srcv, j);
            float w = __shfl_sync(0xffffffffu, nrmv, j);
            float4 v0 = p4[(size_t)s * 64 + lane];
            float4 v1 = p4[(size_t)s * 64 + 32 + lane];
            a0.x += v0.x * w; a0.y += v0.y * w; a0.z += v0.z * w; a0.w += v0.w * w;
            a1.x += v1.x * w; a1.y += v1.y * w; a1.z += v1.z * w; a1.w += v1.w * w;
        }
    }
    float4 b0 = *(const float4 *)(bias + lane * 4);
    float4 b1 = *(const float4 *)(bias + 128 + lane * 4);
    float f[8];
    f[0] = fmaxf(a0.x + b0.x, 0.f); f[1] = fmaxf(a0.y + b0.y, 0.f);
    f[2] = fmaxf(a0.z + b0.z, 0.f); f[3] = fmaxf(a0.w + b0.w, 0.f);
    f[4] = fmaxf(a1.x + b1.x, 0.f); f[5] = fmaxf(a1.y + b1.y, 0.f);
    f[6] = fmaxf(a1.z + b1.z, 0.f); f[7] = fmaxf(a1.w + b1.w, 0.f);
    bf16 h[8], l[8];
#pragma unroll
    for (int j = 0; j < 8; j++) split2(f[j], h[j], l[j]);
    uint2 *hh2 = (uint2 *)hh, *hl2 = (uint2 *)hl;
    hh2[(size_t)warp * 64 + lane]      = make_uint2(pkbf(h[0], h[1]), pkbf(h[2], h[3]));
    hh2[(size_t)warp * 64 + 32 + lane] = make_uint2(pkbf(h[4], h[5]), pkbf(h[6], h[7]));
    hl2[(size_t)warp * 64 + lane]      = make_uint2(pkbf(l[0], l[1]), pkbf(l[2], l[3]));
    hl2[(size_t)warp * 64 + 32 + lane] = make_uint2(pkbf(l[4], l[5]), pkbf(l[6], l[7]));
}

// ---------------- gather layer 2 + reparametrize ----------------
__global__ void k_gather2(const float *__restrict__ pre, const int *__restrict__ rowp,
                          const int *__restrict__ col, const float *__restrict__ dinv,
                          const float *__restrict__ bmu, const float *__restrict__ bls,
                          const float *__restrict__ eps, bf16 *__restrict__ zh,
                          bf16 *__restrict__ zl, float *__restrict__ out,
                          int n, size_t mu_off, size_t ls_off) {
    int warp = (blockIdx.x * blockDim.x + threadIdx.x) >> 5;
    int lane = threadIdx.x & 31;
    if (warp >= n) return;
    const float4 *p4 = (const float4 *)pre;
    float dn = dinv[warp];
    float nn = dn * dn;
    float4 a0 = p4[(size_t)warp * 64 + lane];
    float4 a1 = p4[(size_t)warp * 64 + 32 + lane];
    a0.x *= nn; a0.y *= nn; a0.z *= nn; a0.w *= nn;
    a1.x *= nn; a1.y *= nn; a1.z *= nn; a1.w *= nn;

    int s0 = rowp[warp], s1 = rowp[warp + 1];
    for (int base = s0; base < s1; base += 32) {
        int m = s1 - base; if (m > 32) m = 32;
        int srcv = 0; float nrmv = 0.0f;
        if (lane < m) { srcv = col[base + lane]; nrmv = dinv[srcv] * dn; }
        for (int j = 0; j < m; j++) {
            int s = __shfl_sync(0xffffffffu, srcv, j);
            float w = __shfl_sync(0xffffffffu, nrmv, j);
            float4 v0 = p4[(size_t)s * 64 + lane];
            float4 v1 = p4[(size_t)s * 64 + 32 + lane];
            a0.x += v0.x * w; a0.y += v0.y * w; a0.z += v0.z * w; a0.w += v0.w * w;
            a1.x += v1.x * w; a1.y += v1.y * w; a1.z += v1.z * w; a1.w += v1.w * w;
        }
    }
    float4 bm4 = *(const float4 *)(bmu + lane * 4);
    float4 bl4 = *(const float4 *)(bls + lane * 4);
    float4 mu = make_float4(a0.x + bm4.x, a0.y + bm4.y, a0.z + bm4.z, a0.w + bm4.w);
    float4 ls = make_float4(a1.x + bl4.x, a1.y + bl4.y, a1.z + bl4.z, a1.w + bl4.w);
    float4 ep = ((const float4 *)eps)[(size_t)warp * 32 + lane];
    float z0 = ep.x * __expf(ls.x) + mu.x;
    float z1 = ep.y * __expf(ls.y) + mu.y;
    float z2 = ep.z * __expf(ls.z) + mu.z;
    float z3 = ep.w * __expf(ls.w) + mu.w;
    bf16 h0, h1, h2, h3, l0, l1, l2, l3;
    split2(z0, h0, l0); split2(z1, h1, l1);
    split2(z2, h2, l2); split2(z3, h3, l3);
    ((uint2 *)zh)[(size_t)warp * 32 + lane] = make_uint2(pkbf(h0, h1), pkbf(h2, h3));
    ((uint2 *)zl)[(size_t)warp * 32 + lane] = make_uint2(pkbf(l0, l1), pkbf(l2, l3));
    ((float4 *)(out + mu_off))[(size_t)warp * 32 + lane] = mu;
    ((float4 *)(out + ls_off))[(size_t)warp * 32 + lane] = ls;
}

// ---------------- adj = sigmoid(Z Z^T), HMMA bf16-split, 3-tile 2-phase -------
#define ZSTRIDE 136
#define ZTILE   (128 * ZSTRIDE)
#define ZT_SMEM (3 * ZTILE * 2)

__global__ __launch_bounds__(256, 2)
void k_zzt_mma(const bf16 *__restrict__ zh, const bf16 *__restrict__ zl,
               float *__restrict__ out, int n) {
    extern __shared__ char smem[];
    bf16 *tiles = (bf16 *)smem;

    int i = blockIdx.x;
    int bx = (int)((sqrtf(8.0f * (float)i + 1.0f) - 1.0f) * 0.5f);
    while ((bx + 1) * (bx + 2) / 2 <= i) bx++;
    while (bx * (bx + 1) / 2 > i) bx--;
    int by = i - bx * (bx + 1) / 2;
    const int bm = by * 128, bn = bx * 128;

    const int tid = threadIdx.x;
    const int wid = tid >> 5, lane = tid & 31;
    const int wm = (wid & 3) * 32, wn = (wid >> 2) * 64;
    const int tq = lane >> 2, tr = lane & 3;

    bf16 *Ah = tiles, *Bh = tiles + ZTILE, *T2 = tiles + 2 * ZTILE;

#pragma unroll
    for (int tile = 0; tile < 3; tile++) {
        const bf16 *src = (tile == 2) ? zl : zh;
        int rowoff = (tile == 0) ? bm : bn;
        bf16 *dstt = tiles + tile * ZTILE;
#pragma unroll
        for (int it = 0; it < 8; it++) {
            int idx = tid + it * 256;
            int r = idx >> 4, g = idx & 15;
            uint4 v = *(const uint4 *)(src + (size_t)(rowoff + r) * 128 + g * 8);
            *(uint4 *)(dstt + r * ZSTRIDE + g * 8) = v;
        }
    }
    __syncthreads();

    float c[2][8][4];
#pragma unroll
    for (int mf = 0; mf < 2; mf++)
#pragma unroll
        for (int nf = 0; nf < 8; nf++)
#pragma unroll
            for (int r = 0; r < 4; r++) c[mf][nf][r] = 0.0f;

    // phase 1: acc += Ah*Bh^T + Ah*Bl^T
#pragma unroll
    for (int ks = 0; ks < 8; ks++) {
        int k0 = ks * 16;
        uint32_t ah[2][4];
#pragma unroll
        for (int mf = 0; mf < 2; mf++) {
            int base = (wm + mf * 16 + tq) * ZSTRIDE + k0 + tr * 2;
            ah[mf][0] = *(const uint32_t *)(Ah + base);
            ah[mf][1] = *(const uint32_t *)(Ah + base + 8 * ZSTRIDE);
            ah[mf][2] = *(const uint32_t *)(Ah + base + 8);
            ah[mf][3] = *(const uint32_t *)(Ah + base + 8 * ZSTRIDE + 8);
        }
#pragma unroll
        for (int nf = 0; nf < 8; nf++) {
            int bbase = (wn + nf * 8 + tq) * ZSTRIDE + k0 + tr * 2;
            uint32_t bh0 = *(const uint32_t *)(Bh + bbase);
            uint32_t bh1 = *(const uint32_t *)(Bh + bbase + 8);
            uint32_t bl0 = *(const uint32_t *)(T2 + bbase);
            uint32_t bl1 = *(const uint32_t *)(T2 + bbase + 8);
#pragma unroll
            for (int mf = 0; mf < 2; mf++) {
                mma_bf16(c[mf][nf], ah[mf], bh0, bh1);
                mma_bf16(c[mf][nf], ah[mf], bl0, bl1);
            }
        }
    }

    // reload T2 = Al(bm, zl)
    __syncthreads();
#pragma unroll
    for (int it = 0; it < 8; it++) {
        int idx = tid + it * 256;
        int r = idx >> 4, g = idx & 15;
        uint4 v = *(const uint4 *)(zl + (size_t)(bm + r) * 128 + g * 8);
        *(uint4 *)(T2 + r * ZSTRIDE + g * 8) = v;
    }
    __syncthreads();

    // phase 2: acc += Al*Bh^T
#pragma unroll
    for (int ks = 0; ks < 8; ks++) {
        int k0 = ks * 16;
        uint32_t al[2][4];
#pragma unroll
        for (int mf = 0; mf < 2; mf++) {
            int base = (wm + mf * 16 + tq) * ZSTRIDE + k0 + tr * 2;
            al[mf][0] = *(const uint32_t *)(T2 + base);
            al[mf][1] = *(const uint32_t *)(T2 + base + 8 * ZSTRIDE);
            al[mf][2] = *(const uint32_t *)(T2 + base + 8);
            al[mf][3] = *(const uint32_t *)(T2 + base + 8 * ZSTRIDE + 8);
        }
#pragma unroll
        for (int nf = 0; nf < 8; nf++) {
            int bbase = (wn + nf * 8 + tq) * ZSTRIDE + k0 + tr * 2;
            uint32_t bh0 = *(const uint32_t *)(Bh + bbase);
            uint32_t bh1 = *(const uint32_t *)(Bh + bbase + 8);
#pragma unroll
            for (int mf = 0; mf < 2; mf++)
                mma_bf16(c[mf][nf], al[mf], bh0, bh1);
        }
    }

    // sigmoid via tanh.approx (1 MUFU instead of 2)
#pragma unroll
    for (int mf = 0; mf < 2; mf++)
#pragma unroll
        for (int nf = 0; nf < 8; nf++)
#pragma unroll
            for (int r = 0; r < 4; r++)
                c[mf][nf][r] = fast_sigmoid(c[mf][nf][r]);

#pragma unroll
    for (int mf = 0; mf < 2; mf++)
#pragma unroll
        for (int half = 0; half < 2; half++) {
            int row = bm + wm + mf * 16 + tq + half * 8;
            float *rp = out + (size_t)row * n + bn + wn + tr * 2;
#pragma unroll
            for (int nf = 0; nf < 8; nf++)
                *(float2 *)(rp + nf * 8) =
                    make_float2(c[mf][nf][2 * half], c[mf][nf][2 * half + 1]);
        }

    if (bx == by) return;

    __syncthreads();
    float *sT = (float *)smem;
#pragma unroll
    for (int mf = 0; mf < 2; mf++)
#pragma unroll
        for (int nf = 0; nf < 8; nf++) {
            int colc = wn + nf * 8 + tr * 2;
            int row0 = wm + mf * 16 + tq;
            sT[(colc + 0) * 132 + row0]     = c[mf][nf][0];
            sT[(colc + 1) * 132 + row0]     = c[mf][nf][1];
            sT[(colc + 0) * 132 + row0 + 8] = c[mf][nf][2];
            sT[(colc + 1) * 132 + row0 + 8] = c[mf][nf][3];
        }
    __syncthreads();
#pragma unroll
    for (int it = 0; it < 16; it++) {
        int idx = tid + it * 256;
        int mr = idx >> 5, mc4 = idx & 31;
        float4 v = *(const float4 *)&sT[mr * 132 + mc4 * 4];
        *(float4 *)(out + (size_t)(bn + mr) * n + bm + mc4 * 4) = v;
    }
}

// ---------------- launcher ----------------
extern "C" void kernel_launch(void *const *d_in, const int *in_sizes, int n_in,
                              void *d_out, int out_size) {
    const float *x   = (const float *)d_in[0];
    const int *ei    = (const int *)d_in[1];
    const float *eps = (const float *)d_in[2];
    const float *W1  = (const float *)d_in[3];
    const float *b1  = (const float *)d_in[4];
    const float *Wmu = (const float *)d_in[5];
    const float *bmu = (const float *)d_in[6];
    const float *Wls = (const float *)d_in[7];
    const float *bls = (const float *)d_in[8];
    float *out       = (float *)d_out;

    const int n = in_sizes[0] / IN_DIM;   // 8192
    const int E = in_sizes[1] / 2;        // 262144
    const int *src = ei;
    const int *dst = ei + E;

    float *buf1, *buf3, *dinv;
    bf16 *hh, *hl, *zh, *zl, *w1h, *w1l, *w23h, *w23l;
    int *cnt, *rowp, *priv, *col;
    cudaGetSymbolAddress((void **)&buf1, g_buf1);
    cudaGetSymbolAddress((void **)&buf3, g_buf3);
    cudaGetSymbolAddress((void **)&dinv, g_dinv);
    cudaGetSymbolAddress((void **)&cnt,  g_cnt);
    cudaGetSymbolAddress((void **)&rowp, g_rowp);
    cudaGetSymbolAddress((void **)&priv, g_priv);
    cudaGetSymbolAddress((void **)&col,  g_col);
    cudaGetSymbolAddress((void **)&hh,   g_hh);
    cudaGetSymbolAddress((void **)&hl,   g_hl);
    cudaGetSymbolAddress((void **)&zh,   g_zh);
    cudaGetSymbolAddress((void **)&zl,   g_zl);
    cudaGetSymbolAddress((void **)&w1h,  g_w1t_h);
    cudaGetSymbolAddress((void **)&w1l,  g_w1t_l);
    cudaGetSymbolAddress((void **)&w23h, g_w23t_h);
    cudaGetSymbolAddress((void **)&w23l, g_w23t_l);

    static int smem_set = 0;
    if (!smem_set) {
        cudaFuncSetAttribute(k_zzt_mma, cudaFuncAttributeMaxDynamicSharedMemorySize,
                             ZT_SMEM);
        cudaFuncSetAttribute(k_gemm_bs<0>, cudaFuncAttributeMaxDynamicSharedMemorySize,
                             GSMEM);
        cudaFuncSetAttribute(k_gemm_bs<1>, cudaFuncAttributeMaxDynamicSharedMemorySize,
                             GSMEM);
        smem_set = 1;
    }

    const size_t mu_off = (size_t)n * n;
    const size_t ls_off = mu_off + (size_t)n * LAT;

    // ---- fork: CSR build on side stream ----
    cudaEventRecord(g_side.evFork, 0);
    cudaStreamWaitEvent(g_side.side, g_side.evFork, 0);

    cudaMemsetAsync(priv, 0, NNODE * NCHUNK * sizeof(int), g_side.side);
    k_hist_priv<<<(E + 255) / 256, 256, 0, g_side.side>>>(priv, dst, E);
    k_sum<<<(n * 32 + 255) / 256, 256, 0, g_side.side>>>(priv, cnt, n);
    k_scan<<<1, 1024, 0, g_side.side>>>(cnt, rowp, dinv);
    k_offsets<<<(n * 32 + 255) / 256, 256, 0, g_side.side>>>(priv, rowp, n);
    k_fill_priv<<<(E + 255) / 256, 256, 0, g_side.side>>>(priv, col, src, dst, E);
    cudaEventRecord(g_side.evJoin, g_side.side);

    // ---- main stream: weight conversion + GEMM1 (x split fused in-kernel) ----
    int wthreads = IN_DIM * HID + F2 * HID;
    k_convert_w<<<(wthreads + 255) / 256, 256>>>(W1, Wmu, Wls, w1h, w1l, w23h, w23l);
    k_gemm_bs<1><<<dim3(HID / 128, n / 128), 256, GSMEM>>>(x, nullptr, w1h, w1l,
                                                           buf1, n, HID, IN_DIM);

    // ---- join: gathers need CSR ----
    cudaStreamWaitEvent(0, g_side.evJoin, 0);

    k_gather1<<<(n * 32 + 255) / 256, 256>>>(buf1, hh, hl, rowp, col, dinv, b1, n);
    k_gemm_bs<0><<<dim3(F2 / 128, n / 128), 256, GSMEM>>>(hh, hl, w23h, w23l, buf3,
                                                          n, F2, HID);
    k_gather2<<<(n * 32 + 255) / 256, 256>>>(buf3, rowp, col, dinv, bmu, bls, eps,
                                             zh, zl, out, n, mu_off, ls_off);

    int nt = (n / 128) * (n / 128 + 1) / 2;   // 2080
    k_zzt_mma<<<nt, 256, ZT_SMEM>>>(zh, zl, out, n);
}

// round 13
// speedup vs baseline: 1.0453x; 1.0336x over previous
#include <cuda_runtime.h>
#include <cuda_bf16.h>
#include <math.h>
#include <cstdint>

#define IN_DIM 512
#define HID    256
#define LAT    128
#define F2     256
#define NNODE  8192
#define NEDGE  262144
#define NCHUNK 32          // edges per chunk = 8192 -> chunk = e >> 13

typedef __nv_bfloat16 bf16;

// ---------------- scratch ----------------
__device__ float g_buf1[NNODE * 256];     // GEMM1 out; later reused as z (fp32)
__device__ float g_buf3[NNODE * 256];
__device__ float g_dinv[NNODE];
__device__ int   g_cnt [NNODE];
__device__ int   g_rowp[NNODE + 1];
__device__ int   g_priv[NNODE * NCHUNK];  // [node][chunk]
__device__ int   g_col [NEDGE];
__device__ bf16  g_hh[NNODE * HID];
__device__ bf16  g_hl[NNODE * HID];
__device__ float g_z [NNODE * LAT];
__device__ bf16  g_w1t_h[256 * 512];
__device__ bf16  g_w1t_l[256 * 512];
__device__ bf16  g_w23t_h[256 * 256];
__device__ bf16  g_w23t_l[256 * 256];

// ---------------- side stream / events ----------------
struct SideInit {
    cudaStream_t side;
    cudaEvent_t evFork, evJoin;
    SideInit() {
        cudaStreamCreateWithFlags(&side, cudaStreamNonBlocking);
        cudaEventCreateWithFlags(&evFork, cudaEventDisableTiming);
        cudaEventCreateWithFlags(&evJoin, cudaEventDisableTiming);
    }
};
static SideInit g_side;

// ---------------- helpers ----------------
__device__ __forceinline__ void split2(float v, bf16 &h, bf16 &l) {
    h = __float2bfloat16(v);
    l = __float2bfloat16(v - __bfloat162float(h));
}
__device__ __forceinline__ uint32_t pkbf(bf16 a, bf16 b) {
    return (uint32_t)__bfloat16_as_ushort(a) | ((uint32_t)__bfloat16_as_ushort(b) << 16);
}
__device__ __forceinline__ float fast_sigmoid(float x) {
    float t;
    asm("tanh.approx.f32 %0, %1;" : "=f"(t) : "f"(x * 0.5f));
    return fmaf(0.5f, t, 0.5f);
}
__device__ __forceinline__ uint32_t to_tf32(float v) {
    uint32_t r;
    asm("cvt.rna.tf32.f32 %0, %1;" : "=r"(r) : "f"(v));
    return r;
}
__device__ __forceinline__ void mma_bf16(float *d, const uint32_t *a,
                                         uint32_t b0, uint32_t b1) {
    asm volatile(
        "mma.sync.aligned.m16n8k16.row.col.f32.bf16.bf16.f32 "
        "{%0,%1,%2,%3}, {%4,%5,%6,%7}, {%8,%9}, {%0,%1,%2,%3};"
        : "+f"(d[0]), "+f"(d[1]), "+f"(d[2]), "+f"(d[3])
        : "r"(a[0]), "r"(a[1]), "r"(a[2]), "r"(a[3]), "r"(b0), "r"(b1));
}
__device__ __forceinline__ void mma_tf32(float *d, const uint32_t *a,
                                         uint32_t b0, uint32_t b1) {
    asm volatile(
        "mma.sync.aligned.m16n8k8.row.col.f32.tf32.tf32.f32 "
        "{%0,%1,%2,%3}, {%4,%5,%6,%7}, {%8,%9}, {%0,%1,%2,%3};"
        : "+f"(d[0]), "+f"(d[1]), "+f"(d[2]), "+f"(d[3])
        : "r"(a[0]), "r"(a[1]), "r"(a[2]), "r"(a[3]), "r"(b0), "r"(b1));
}

// ---------------- CSR build (privatized [node][chunk], warp-per-node scan) ----
__global__ void k_hist_priv(int *priv, const int *__restrict__ dst, int E) {
    int e = blockIdx.x * 256 + threadIdx.x;
    if (e < E) atomicAdd(&priv[dst[e] * NCHUNK + (e >> 13)], 1);
}
__global__ void k_sum(const int *__restrict__ priv, int *cnt, int n) {
    int warp = (blockIdx.x * blockDim.x + threadIdx.x) >> 5;
    int lane = threadIdx.x & 31;
    if (warp >= n) return;
    int v = priv[warp * NCHUNK + lane];
#pragma unroll
    for (int o = 16; o; o >>= 1) v += __shfl_xor_sync(0xffffffffu, v, o);
    if (lane == 0) cnt[warp] = v;
}
__global__ void k_scan(const int *__restrict__ cnt, int *rowp, float *dinv) {
    __shared__ int sm[1024];
    int t = threadIdx.x;
    int loc[8]; int s = 0;
#pragma unroll
    for (int j = 0; j < 8; j++) { loc[j] = s; s += cnt[t * 8 + j]; }
    sm[t] = s;
    __syncthreads();
    int v = s;
    for (int off = 1; off < 1024; off <<= 1) {
        int add = (t >= off) ? sm[t - off] : 0;
        __syncthreads();
        v += add; sm[t] = v;
        __syncthreads();
    }
    int exc = v - s;
#pragma unroll
    for (int j = 0; j < 8; j++) {
        rowp[t * 8 + j] = exc + loc[j];
        dinv[t * 8 + j] = rsqrtf((float)cnt[t * 8 + j] + 1.0f);
    }
    if (t == 1023) rowp[NNODE] = v;
}
__global__ void k_offsets(int *priv, const int *__restrict__ rowp, int n) {
    int warp = (blockIdx.x * blockDim.x + threadIdx.x) >> 5;
    int lane = threadIdx.x & 31;
    if (warp >= n) return;
    int v = priv[warp * NCHUNK + lane];
    int s = v;
#pragma unroll
    for (int o = 1; o < 32; o <<= 1) {
        int t = __shfl_up_sync(0xffffffffu, s, o);
        if (lane >= o) s += t;
    }
    priv[warp * NCHUNK + lane] = rowp[warp] + s - v;
}
__global__ void k_fill_priv(int *priv, int *col, const int *__restrict__ src,
                            const int *__restrict__ dst, int E) {
    int e = blockIdx.x * 256 + threadIdx.x;
    if (e >= E) return;
    int slot = atomicAdd(&priv[dst[e] * NCHUNK + (e >> 13)], 1);
    col[slot] = src[e];
}

// ---------------- weight conversions ----------------
__global__ void k_convert_w(const float *__restrict__ W1, const float *__restrict__ Wmu,
                            const float *__restrict__ Wls,
                            bf16 *__restrict__ w1h, bf16 *__restrict__ w1l,
                            bf16 *__restrict__ w23h, bf16 *__restrict__ w23l) {
    int t = blockIdx.x * 256 + threadIdx.x;
    if (t < IN_DIM * HID) {
        int k = t >> 8, c = t & 255;
        bf16 h, l;
        split2(W1[t], h, l);
        w1h[c * IN_DIM + k] = h;
        w1l[c * IN_DIM + k] = l;
        return;
    }
    t -= IN_DIM * HID;
    if (t < F2 * HID) {
        int nn = t >> 8, k = t & 255;
        float v = (nn < LAT) ? Wmu[k * LAT + nn] : Wls[k * LAT + (nn - LAT)];
        bf16 h, l;
        split2(v, h, l);
        w23h[t] = h; w23l[t] = l;
    }
}

// ---------------- bf16-split HMMA GEMM: C[M,N] = A[M,K] @ B[N,K]^T ------------
// Tile 128x128, 8 warps (4m x 2n), BK=64.  (R10 proven config)
#define GS 72
#define GTILE (128 * GS)
#define GSMEM (4 * GTILE * 2)

template <int SPLITA>
__global__ __launch_bounds__(256, 1)
void k_gemm_bs(const void *__restrict__ Aq, const bf16 *__restrict__ Albf,
               const bf16 *__restrict__ Bh, const bf16 *__restrict__ Bl,
               float *__restrict__ C, int M, int N, int K) {
    extern __shared__ char smem[];
    bf16 *sAh = (bf16 *)smem;
    bf16 *sAl = sAh + GTILE;
    bf16 *sBh = sAl + GTILE;
    bf16 *sBl = sBh + GTILE;
    const int tid = threadIdx.x;
    const int wid = tid >> 5, lane = tid & 31;
    const int bm = blockIdx.y * 128, bn = blockIdx.x * 128;
    const int wm = (wid & 3) * 32, wn = (wid >> 2) * 64;
    const int tq = lane >> 2, tr = lane & 3;

    float c[2][8][4];
#pragma unroll
    for (int mf = 0; mf < 2; mf++)
#pragma unroll
        for (int nf = 0; nf < 8; nf++)
#pragma unroll
            for (int r = 0; r < 4; r++) c[mf][nf][r] = 0.0f;

    for (int kc = 0; kc < K; kc += 64) {
#pragma unroll
        for (int it = 0; it < 4; it++) {
            int idx = tid + it * 256;
            int r = idx >> 3, g = idx & 7;
            int doff = r * GS + g * 8;
            if (SPLITA) {
                const float *ap = (const float *)Aq + (size_t)(bm + r) * K + kc + g * 8;
                float4 v0 = *(const float4 *)ap;
                float4 v1 = *(const float4 *)(ap + 4);
                bf16 h[8], l[8];
                split2(v0.x, h[0], l[0]); split2(v0.y, h[1], l[1]);
                split2(v0.z, h[2], l[2]); split2(v0.w, h[3], l[3]);
                split2(v1.x, h[4], l[4]); split2(v1.y, h[5], l[5]);
                split2(v1.z, h[6], l[6]); split2(v1.w, h[7], l[7]);
                *(uint4 *)(sAh + doff) = make_uint4(pkbf(h[0], h[1]), pkbf(h[2], h[3]),
                                                    pkbf(h[4], h[5]), pkbf(h[6], h[7]));
                *(uint4 *)(sAl + doff) = make_uint4(pkbf(l[0], l[1]), pkbf(l[2], l[3]),
                                                    pkbf(l[4], l[5]), pkbf(l[6], l[7]));
            } else {
                size_t aoff = (size_t)(bm + r) * K + kc + g * 8;
                *(uint4 *)(sAh + doff) = *(const uint4 *)((const bf16 *)Aq + aoff);
                *(uint4 *)(sAl + doff) = *(const uint4 *)(Albf + aoff);
            }
            size_t boff = (size_t)(bn + r) * K + kc + g * 8;
            *(uint4 *)(sBh + doff) = *(const uint4 *)(Bh + boff);
            *(uint4 *)(sBl + doff) = *(const uint4 *)(Bl + boff);
        }
        __syncthreads();
#pragma unroll
        for (int ks = 0; ks < 4; ks++) {
            int k0 = ks * 16;
            uint32_t ah[2][4], al[2][4];
#pragma unroll
            for (int mf = 0; mf < 2; mf++) {
                int base = (wm + mf * 16 + tq) * GS + k0 + tr * 2;
                ah[mf][0] = *(const uint32_t *)(sAh + base);
                ah[mf][1] = *(const uint32_t *)(sAh + base + 8 * GS);
                ah[mf][2] = *(const uint32_t *)(sAh + base + 8);
                ah[mf][3] = *(const uint32_t *)(sAh + base + 8 * GS + 8);
                al[mf][0] = *(const uint32_t *)(sAl + base);
                al[mf][1] = *(const uint32_t *)(sAl + base + 8 * GS);
                al[mf][2] = *(const uint32_t *)(sAl + base + 8);
                al[mf][3] = *(const uint32_t *)(sAl + base + 8 * GS + 8);
            }
#pragma unroll
            for (int nf = 0; nf < 8; nf++) {
                int bbase = (wn + nf * 8 + tq) * GS + k0 + tr * 2;
                uint32_t bh0 = *(const uint32_t *)(sBh + bbase);
                uint32_t bh1 = *(const uint32_t *)(sBh + bbase + 8);
                uint32_t bl0 = *(const uint32_t *)(sBl + bbase);
                uint32_t bl1 = *(const uint32_t *)(sBl + bbase + 8);
#pragma unroll
                for (int mf = 0; mf < 2; mf++) {
                    mma_bf16(c[mf][nf], ah[mf], bh0, bh1);
                    mma_bf16(c[mf][nf], ah[mf], bl0, bl1);
                    mma_bf16(c[mf][nf], al[mf], bh0, bh1);
                }
            }
        }
        __syncthreads();
    }
#pragma unroll
    for (int mf = 0; mf < 2; mf++)
#pragma unroll
        for (int half = 0; half < 2; half++) {
            int row = bm + wm + mf * 16 + tq + half * 8;
            float *rp = C + (size_t)row * N + bn + wn + tr * 2;
#pragma unroll
            for (int nf = 0; nf < 8; nf++)
                *(float2 *)(rp + nf * 8) =
                    make_float2(c[mf][nf][2 * half], c[mf][nf][2 * half + 1]);
        }
}

// ---------------- gather layer 1 ----------------
__global__ void k_gather1(const float *__restrict__ pre, bf16 *__restrict__ hh,
                          bf16 *__restrict__ hl, const int *__restrict__ rowp,
                          const int *__restrict__ col, const float *__restrict__ dinv,
                          const float *__restrict__ bias, int n) {
    int warp = (blockIdx.x * blockDim.x + threadIdx.x) >> 5;
    int lane = threadIdx.x & 31;
    if (warp >= n) return;
    const float4 *p4 = (const float4 *)pre;
    float dn = dinv[warp];
    float nn = dn * dn;
    float4 a0 = p4[(size_t)warp * 64 + lane];
    float4 a1 = p4[(size_t)warp * 64 + 32 + lane];
    a0.x *= nn; a0.y *= nn; a0.z *= nn; a0.w *= nn;
    a1.x *= nn; a1.y *= nn; a1.z *= nn; a1.w *= nn;

    int s0 = rowp[warp], s1 = rowp[warp + 1];
    for (int base = s0; base < s1; base += 32) {
        int m = s1 - base; if (m > 32) m = 32;
        int srcv = 0; float nrmv = 0.0f;
        if (lane < m) { srcv = col[base + lane]; nrmv = dinv[srcv] * dn; }
        for (int j = 0; j < m; j++) {
            int s = __shfl_sync(0xffffffffu, srcv, j);
            float w = __shfl_sync(0xffffffffu, nrmv, j);
            float4 v0 = p4[(size_t)s * 64 + lane];
            float4 v1 = p4[(size_t)s * 64 + 32 + lane];
            a0.x += v0.x * w; a0.y += v0.y * w; a0.z += v0.z * w; a0.w += v0.w * w;
            a1.x += v1.x * w; a1.y += v1.y * w; a1.z += v1.z * w; a1.w += v1.w * w;
        }
    }
    float4 b0 = *(const float4 *)(bias + lane * 4);
    float4 b1 = *(const float4 *)(bias + 128 + lane * 4);
    float f[8];
    f[0] = fmaxf(a0.x + b0.x, 0.f); f[1] = fmaxf(a0.y + b0.y, 0.f);
    f[2] = fmaxf(a0.z + b0.z, 0.f); f[3] = fmaxf(a0.w + b0.w, 0.f);
    f[4] = fmaxf(a1.x + b1.x, 0.f); f[5] = fmaxf(a1.y + b1.y, 0.f);
    f[6] = fmaxf(a1.z + b1.z, 0.f); f[7] = fmaxf(a1.w + b1.w, 0.f);
    bf16 h[8], l[8];
#pragma unroll
    for (int j = 0; j < 8; j++) split2(f[j], h[j], l[j]);
    uint2 *hh2 = (uint2 *)hh, *hl2 = (uint2 *)hl;
    hh2[(size_t)warp * 64 + lane]      = make_uint2(pkbf(h[0], h[1]), pkbf(h[2], h[3]));
    hh2[(size_t)warp * 64 + 32 + lane] = make_uint2(pkbf(h[4], h[5]), pkbf(h[6], h[7]));
    hl2[(size_t)warp * 64 + lane]      = make_uint2(pkbf(l[0], l[1]), pkbf(l[2], l[3]));
    hl2[(size_t)warp * 64 + 32 + lane] = make_uint2(pkbf(l[4], l[5]), pkbf(l[6], l[7]));
}

// ---------------- gather layer 2 + reparametrize (z stays fp32) ---------------
__global__ void k_gather2(const float *__restrict__ pre, const int *__restrict__ rowp,
                          const int *__restrict__ col, const float *__restrict__ dinv,
                          const float *__restrict__ bmu, const float *__restrict__ bls,
                          const float *__restrict__ eps, float *__restrict__ z,
                          float *__restrict__ out,
                          int n, size_t mu_off, size_t ls_off) {
    int warp = (blockIdx.x * blockDim.x + threadIdx.x) >> 5;
    int lane = threadIdx.x & 31;
    if (warp >= n) return;
    const float4 *p4 = (const float4 *)pre;
    float dn = dinv[warp];
    float nn = dn * dn;
    float4 a0 = p4[(size_t)warp * 64 + lane];
    float4 a1 = p4[(size_t)warp * 64 + 32 + lane];
    a0.x *= nn; a0.y *= nn; a0.z *= nn; a0.w *= nn;
    a1.x *= nn; a1.y *= nn; a1.z *= nn; a1.w *= nn;

    int s0 = rowp[warp], s1 = rowp[warp + 1];
    for (int base = s0; base < s1; base += 32) {
        int m = s1 - base; if (m > 32) m = 32;
        int srcv = 0; float nrmv = 0.0f;
        if (lane < m) { srcv = col[base + lane]; nrmv = dinv[srcv] * dn; }
        for (int j = 0; j < m; j++) {
            int s = __shfl_sync(0xffffffffu, srcv, j);
            float w = __shfl_sync(0xffffffffu, nrmv, j);
            float4 v0 = p4[(size_t)s * 64 + lane];
            float4 v1 = p4[(size_t)s * 64 + 32 + lane];
            a0.x += v0.x * w; a0.y += v0.y * w; a0.z += v0.z * w; a0.w += v0.w * w;
            a1.x += v1.x * w; a1.y += v1.y * w; a1.z += v1.z * w; a1.w += v1.w * w;
        }
    }
    float4 bm4 = *(const float4 *)(bmu + lane * 4);
    float4 bl4 = *(const float4 *)(bls + lane * 4);
    float4 mu = make_float4(a0.x + bm4.x, a0.y + bm4.y, a0.z + bm4.z, a0.w + bm4.w);
    float4 ls = make_float4(a1.x + bl4.x, a1.y + bl4.y, a1.z + bl4.z, a1.w + bl4.w);
    float4 ep = ((const float4 *)eps)[(size_t)warp * 32 + lane];
    float4 zz;
    zz.x = ep.x * __expf(ls.x) + mu.x;
    zz.y = ep.y * __expf(ls.y) + mu.y;
    zz.z = ep.z * __expf(ls.z) + mu.z;
    zz.w = ep.w * __expf(ls.w) + mu.w;
    ((float4 *)z)[(size_t)warp * 32 + lane] = zz;
    ((float4 *)(out + mu_off))[(size_t)warp * 32 + lane] = mu;
    ((float4 *)(out + ls_off))[(size_t)warp * 32 + lane] = ls;
}

// ---------------- adj = sigmoid(Z Z^T), TF32 single-term, K 2-chunk ----------
// smem: 2 fp32 tiles of 128 x 68 (64 k + 4 pad) = 69632 B -> 2 CTAs/SM.
#define ZS4 68
#define ZTILE4 (128 * ZS4)
#define ZT_SMEM (2 * ZTILE4 * 4)

__global__ __launch_bounds__(256, 2)
void k_zzt_tf32(const float *__restrict__ z, float *__restrict__ out, int n) {
    extern __shared__ char smem[];
    uint32_t *sA = (uint32_t *)smem;               // tf32 bit patterns
    uint32_t *sB = sA + ZTILE4;

    int i = blockIdx.x;
    int bx = (int)((sqrtf(8.0f * (float)i + 1.0f) - 1.0f) * 0.5f);
    while ((bx + 1) * (bx + 2) / 2 <= i) bx++;
    while (bx * (bx + 1) / 2 > i) bx--;
    int by = i - bx * (bx + 1) / 2;
    const int bm = by * 128, bn = bx * 128;

    const int tid = threadIdx.x;
    const int wid = tid >> 5, lane = tid & 31;
    const int wm = (wid & 3) * 32, wn = (wid >> 2) * 64;
    const int tq = lane >> 2, tr = lane & 3;

    float c[2][8][4];
#pragma unroll
    for (int mf = 0; mf < 2; mf++)
#pragma unroll
        for (int nf = 0; nf < 8; nf++)
#pragma unroll
            for (int r = 0; r < 4; r++) c[mf][nf][r] = 0.0f;

#pragma unroll
    for (int kc = 0; kc < LAT; kc += 64) {
        if (kc) __syncthreads();                    // protect smem reuse
        // load A rows [bm,128) cols [kc, kc+64), B rows [bn,128): fp32 -> tf32
#pragma unroll
        for (int it = 0; it < 8; it++) {
            int idx = tid + it * 256;               // 2048 float4 groups per tile
            int r = idx >> 4, g = idx & 15;
            float4 va = *(const float4 *)(z + (size_t)(bm + r) * LAT + kc + g * 4);
            float4 vb = *(const float4 *)(z + (size_t)(bn + r) * LAT + kc + g * 4);
            int doff = r * ZS4 + g * 4;
            sA[doff + 0] = to_tf32(va.x); sA[doff + 1] = to_tf32(va.y);
            sA[doff + 2] = to_tf32(va.z); sA[doff + 3] = to_tf32(va.w);
            sB[doff + 0] = to_tf32(vb.x); sB[doff + 1] = to_tf32(vb.y);
            sB[doff + 2] = to_tf32(vb.z); sB[doff + 3] = to_tf32(vb.w);
        }
        __syncthreads();
#pragma unroll
        for (int ks = 0; ks < 8; ks++) {
            int k0 = ks * 8;
            uint32_t a[2][4];
#pragma unroll
            for (int mf = 0; mf < 2; mf++) {
                int base = (wm + mf * 16 + tq) * ZS4 + k0 + tr;
                a[mf][0] = sA[base];
                a[mf][1] = sA[base + 8 * ZS4];
                a[mf][2] = sA[base + 4];
                a[mf][3] = sA[base + 8 * ZS4 + 4];
            }
#pragma unroll
            for (int nf = 0; nf < 8; nf++) {
                int bbase = (wn + nf * 8 + tq) * ZS4 + k0 + tr;
                uint32_t b0 = sB[bbase];
                uint32_t b1 = sB[bbase + 4];
#pragma unroll
                for (int mf = 0; mf < 2; mf++)
                    mma_tf32(c[mf][nf], a[mf], b0, b1);
            }
        }
    }

    // sigmoid via tanh.approx
#pragma unroll
    for (int mf = 0; mf < 2; mf++)
#pragma unroll
        for (int nf = 0; nf < 8; nf++)
#pragma unroll
            for (int r = 0; r < 4; r++)
                c[mf][nf][r] = fast_sigmoid(c[mf][nf][r]);

    // direct tile (by,bx)
#pragma unroll
    for (int mf = 0; mf < 2; mf++)
#pragma unroll
        for (int half = 0; half < 2; half++) {
            int row = bm + wm + mf * 16 + tq + half * 8;
            float *rp = out + (size_t)row * n + bn + wn + tr * 2;
#pragma unroll
            for (int nf = 0; nf < 8; nf++)
                *(float2 *)(rp + nf * 8) =
                    make_float2(c[mf][nf][2 * half], c[mf][nf][2 * half + 1]);
        }

    if (bx == by) return;

    // mirror tile via smem transpose ([128][132] floats = 67584 B <= 69632)
    __syncthreads();
    float *sT = (float *)smem;
#pragma unroll
    for (int mf = 0; mf < 2; mf++)
#pragma unroll
        for (int nf = 0; nf < 8; nf++) {
            int colc = wn + nf * 8 + tr * 2;
            int row0 = wm + mf * 16 + tq;
            sT[(colc + 0) * 132 + row0]     = c[mf][nf][0];
            sT[(colc + 1) * 132 + row0]     = c[mf][nf][1];
            sT[(colc + 0) * 132 + row0 + 8] = c[mf][nf][2];
            sT[(colc + 1) * 132 + row0 + 8] = c[mf][nf][3];
        }
    __syncthreads();
#pragma unroll
    for (int it = 0; it < 16; it++) {
        int idx = tid + it * 256;
        int mr = idx >> 5, mc4 = idx & 31;
        float4 v = *(const float4 *)&sT[mr * 132 + mc4 * 4];
        *(float4 *)(out + (size_t)(bn + mr) * n + bm + mc4 * 4) = v;
    }
}

// ---------------- launcher ----------------
extern "C" void kernel_launch(void *const *d_in, const int *in_sizes, int n_in,
                              void *d_out, int out_size) {
    const float *x   = (const float *)d_in[0];
    const int *ei    = (const int *)d_in[1];
    const float *eps = (const float *)d_in[2];
    const float *W1  = (const float *)d_in[3];
    const float *b1  = (const float *)d_in[4];
    const float *Wmu = (const float *)d_in[5];
    const float *bmu = (const float *)d_in[6];
    const float *Wls = (const float *)d_in[7];
    const float *bls = (const float *)d_in[8];
    float *out       = (float *)d_out;

    const int n = in_sizes[0] / IN_DIM;   // 8192
    const int E = in_sizes[1] / 2;        // 262144
    const int *src = ei;
    const int *dst = ei + E;

    float *buf1, *buf3, *dinv, *zbuf;
    bf16 *hh, *hl, *w1h, *w1l, *w23h, *w23l;
    int *cnt, *rowp, *priv, *col;
    cudaGetSymbolAddress((void **)&buf1, g_buf1);
    cudaGetSymbolAddress((void **)&buf3, g_buf3);
    cudaGetSymbolAddress((void **)&dinv, g_dinv);
    cudaGetSymbolAddress((void **)&zbuf, g_z);
    cudaGetSymbolAddress((void **)&cnt,  g_cnt);
    cudaGetSymbolAddress((void **)&rowp, g_rowp);
    cudaGetSymbolAddress((void **)&priv, g_priv);
    cudaGetSymbolAddress((void **)&col,  g_col);
    cudaGetSymbolAddress((void **)&hh,   g_hh);
    cudaGetSymbolAddress((void **)&hl,   g_hl);
    cudaGetSymbolAddress((void **)&w1h,  g_w1t_h);
    cudaGetSymbolAddress((void **)&w1l,  g_w1t_l);
    cudaGetSymbolAddress((void **)&w23h, g_w23t_h);
    cudaGetSymbolAddress((void **)&w23l, g_w23t_l);

    static int smem_set = 0;
    if (!smem_set) {
        cudaFuncSetAttribute(k_zzt_tf32, cudaFuncAttributeMaxDynamicSharedMemorySize,
                             ZT_SMEM);
        cudaFuncSetAttribute(k_gemm_bs<0>, cudaFuncAttributeMaxDynamicSharedMemorySize,
                             GSMEM);
        cudaFuncSetAttribute(k_gemm_bs<1>, cudaFuncAttributeMaxDynamicSharedMemorySize,
                             GSMEM);
        smem_set = 1;
    }

    const size_t mu_off = (size_t)n * n;
    const size_t ls_off = mu_off + (size_t)n * LAT;

    // ---- fork: CSR build on side stream ----
    cudaEventRecord(g_side.evFork, 0);
    cudaStreamWaitEvent(g_side.side, g_side.evFork, 0);

    cudaMemsetAsync(priv, 0, NNODE * NCHUNK * sizeof(int), g_side.side);
    k_hist_priv<<<(E + 255) / 256, 256, 0, g_side.side>>>(priv, dst, E);
    k_sum<<<(n * 32 + 255) / 256, 256, 0, g_side.side>>>(priv, cnt, n);
    k_scan<<<1, 1024, 0, g_side.side>>>(cnt, rowp, dinv);
    k_offsets<<<(n * 32 + 255) / 256, 256, 0, g_side.side>>>(priv, rowp, n);
    k_fill_priv<<<(E + 255) / 256, 256, 0, g_side.side>>>(priv, col, src, dst, E);
    cudaEventRecord(g_side.evJoin, g_side.side);

    // ---- main stream: weight conversion + GEMM1 (x split fused in-kernel) ----
    int wthreads = IN_DIM * HID + F2 * HID;
    k_convert_w<<<(wthreads + 255) / 256, 256>>>(W1, Wmu, Wls, w1h, w1l, w23h, w23l);
    k_gemm_bs<1><<<dim3(HID / 128, n / 128), 256, GSMEM>>>(x, nullptr, w1h, w1l,
                                                           buf1, n, HID, IN_DIM);

    // ---- join: gathers need CSR ----
    cudaStreamWaitEvent(0, g_side.evJoin, 0);

    k_gather1<<<(n * 32 + 255) / 256, 256>>>(buf1, hh, hl, rowp, col, dinv, b1, n);
    k_gemm_bs<0><<<dim3(F2 / 128, n / 128), 256, GSMEM>>>(hh, hl, w23h, w23l, buf3,
                                                          n, F2, HID);
    k_gather2<<<(n * 32 + 255) / 256, 256>>>(buf3, rowp, col, dinv, bmu, bls, eps,
                                             zbuf, out, n, mu_off, ls_off);

    int nt = (n / 128) * (n / 128 + 1) / 2;   // 2080
    k_zzt_tf32<<<nt, 256, ZT_SMEM>>>(zbuf, out, n);
}

// round 14
// speedup vs baseline: 1.0971x; 1.0496x over previous
#include <cuda_runtime.h>
#include <cuda_bf16.h>
#include <cuda_fp16.h>
#include <math.h>
#include <cstdint>

#define IN_DIM 512
#define HID    256
#define LAT    128
#define F2     256
#define NNODE  8192
#define NEDGE  262144
#define NCHUNK 32          // edges per chunk = 8192 -> chunk = e >> 13

typedef __nv_bfloat16 bf16;

// ---------------- scratch ----------------
__device__ __half g_pre1[NNODE * 256];    // GEMM outputs (fp16)
__device__ __half g_pre3[NNODE * 256];
__device__ float g_dinv[NNODE];
__device__ int   g_cnt [NNODE];
__device__ int   g_rowp[NNODE + 1];
__device__ int   g_priv[NNODE * NCHUNK];  // [node][chunk]
__device__ int   g_col [NEDGE];
__device__ bf16  g_hh[NNODE * HID];
__device__ bf16  g_hl[NNODE * HID];
__device__ float g_z [NNODE * LAT];
__device__ bf16  g_w1t_h[256 * 512];
__device__ bf16  g_w1t_l[256 * 512];
__device__ bf16  g_w23t_h[256 * 256];
__device__ bf16  g_w23t_l[256 * 256];

// ---------------- side stream / events ----------------
struct SideInit {
    cudaStream_t side;
    cudaEvent_t evFork, evJoin;
    SideInit() {
        cudaStreamCreateWithFlags(&side, cudaStreamNonBlocking);
        cudaEventCreateWithFlags(&evFork, cudaEventDisableTiming);
        cudaEventCreateWithFlags(&evJoin, cudaEventDisableTiming);
    }
};
static SideInit g_side;

// ---------------- helpers ----------------
__device__ __forceinline__ void split2(float v, bf16 &h, bf16 &l) {
    h = __float2bfloat16(v);
    l = __float2bfloat16(v - __bfloat162float(h));
}
__device__ __forceinline__ uint32_t pkbf(bf16 a, bf16 b) {
    return (uint32_t)__bfloat16_as_ushort(a) | ((uint32_t)__bfloat16_as_ushort(b) << 16);
}
__device__ __forceinline__ float fast_sigmoid(float x) {
    float t;
    asm("tanh.approx.f32 %0, %1;" : "=f"(t) : "f"(x * 0.5f));
    return fmaf(0.5f, t, 0.5f);
}
__device__ __forceinline__ uint32_t to_tf32(float v) {
    uint32_t r;
    asm("cvt.rna.tf32.f32 %0, %1;" : "=r"(r) : "f"(v));
    return r;
}
__device__ __forceinline__ void mma_bf16(float *d, const uint32_t *a,
                                         uint32_t b0, uint32_t b1) {
    asm volatile(
        "mma.sync.aligned.m16n8k16.row.col.f32.bf16.bf16.f32 "
        "{%0,%1,%2,%3}, {%4,%5,%6,%7}, {%8,%9}, {%0,%1,%2,%3};"
        : "+f"(d[0]), "+f"(d[1]), "+f"(d[2]), "+f"(d[3])
        : "r"(a[0]), "r"(a[1]), "r"(a[2]), "r"(a[3]), "r"(b0), "r"(b1));
}
__device__ __forceinline__ void mma_tf32(float *d, const uint32_t *a,
                                         uint32_t b0, uint32_t b1) {
    asm volatile(
        "mma.sync.aligned.m16n8k8.row.col.f32.tf32.tf32.f32 "
        "{%0,%1,%2,%3}, {%4,%5,%6,%7}, {%8,%9}, {%0,%1,%2,%3};"
        : "+f"(d[0]), "+f"(d[1]), "+f"(d[2]), "+f"(d[3])
        : "r"(a[0]), "r"(a[1]), "r"(a[2]), "r"(a[3]), "r"(b0), "r"(b1));
}

// ---------------- CSR build (privatized [node][chunk], warp-per-node scan) ----
__global__ void k_hist_priv(int *priv, const int *__restrict__ dst, int E) {
    int e = blockIdx.x * 256 + threadIdx.x;
    if (e < E) atomicAdd(&priv[dst[e] * NCHUNK + (e >> 13)], 1);
}
__global__ void k_sum(const int *__restrict__ priv, int *cnt, int n) {
    int warp = (blockIdx.x * blockDim.x + threadIdx.x) >> 5;
    int lane = threadIdx.x & 31;
    if (warp >= n) return;
    int v = priv[warp * NCHUNK + lane];
#pragma unroll
    for (int o = 16; o; o >>= 1) v += __shfl_xor_sync(0xffffffffu, v, o);
    if (lane == 0) cnt[warp] = v;
}
__global__ void k_scan(const int *__restrict__ cnt, int *rowp, float *dinv) {
    __shared__ int sm[1024];
    int t = threadIdx.x;
    int loc[8]; int s = 0;
#pragma unroll
    for (int j = 0; j < 8; j++) { loc[j] = s; s += cnt[t * 8 + j]; }
    sm[t] = s;
    __syncthreads();
    int v = s;
    for (int off = 1; off < 1024; off <<= 1) {
        int add = (t >= off) ? sm[t - off] : 0;
        __syncthreads();
        v += add; sm[t] = v;
        __syncthreads();
    }
    int exc = v - s;
#pragma unroll
    for (int j = 0; j < 8; j++) {
        rowp[t * 8 + j] = exc + loc[j];
        dinv[t * 8 + j] = rsqrtf((float)cnt[t * 8 + j] + 1.0f);
    }
    if (t == 1023) rowp[NNODE] = v;
}
__global__ void k_offsets(int *priv, const int *__restrict__ rowp, int n) {
    int warp = (blockIdx.x * blockDim.x + threadIdx.x) >> 5;
    int lane = threadIdx.x & 31;
    if (warp >= n) return;
    int v = priv[warp * NCHUNK + lane];
    int s = v;
#pragma unroll
    for (int o = 1; o < 32; o <<= 1) {
        int t = __shfl_up_sync(0xffffffffu, s, o);
        if (lane >= o) s += t;
    }
    priv[warp * NCHUNK + lane] = rowp[warp] + s - v;
}
__global__ void k_fill_priv(int *priv, int *col, const int *__restrict__ src,
                            const int *__restrict__ dst, int E) {
    int e = blockIdx.x * 256 + threadIdx.x;
    if (e >= E) return;
    int slot = atomicAdd(&priv[dst[e] * NCHUNK + (e >> 13)], 1);
    col[slot] = src[e];
}

// ---------------- weight conversions ----------------
__global__ void k_convert_w(const float *__restrict__ W1, const float *__restrict__ Wmu,
                            const float *__restrict__ Wls,
                            bf16 *__restrict__ w1h, bf16 *__restrict__ w1l,
                            bf16 *__restrict__ w23h, bf16 *__restrict__ w23l) {
    int t = blockIdx.x * 256 + threadIdx.x;
    if (t < IN_DIM * HID) {
        int k = t >> 8, c = t & 255;
        bf16 h, l;
        split2(W1[t], h, l);
        w1h[c * IN_DIM + k] = h;
        w1l[c * IN_DIM + k] = l;
        return;
    }
    t -= IN_DIM * HID;
    if (t < F2 * HID) {
        int nn = t >> 8, k = t & 255;
        float v = (nn < LAT) ? Wmu[k * LAT + nn] : Wls[k * LAT + (nn - LAT)];
        bf16 h, l;
        split2(v, h, l);
        w23h[t] = h; w23l[t] = l;
    }
}

// ---------------- bf16-split HMMA GEMM: C[M,N] = A[M,K] @ B[N,K]^T, C fp16 ----
#define GS 72
#define GTILE (128 * GS)
#define GSMEM (4 * GTILE * 2)

template <int SPLITA>
__global__ __launch_bounds__(256, 1)
void k_gemm_bs(const void *__restrict__ Aq, const bf16 *__restrict__ Albf,
               const bf16 *__restrict__ Bh, const bf16 *__restrict__ Bl,
               __half *__restrict__ C, int M, int N, int K) {
    extern __shared__ char smem[];
    bf16 *sAh = (bf16 *)smem;
    bf16 *sAl = sAh + GTILE;
    bf16 *sBh = sAl + GTILE;
    bf16 *sBl = sBh + GTILE;
    const int tid = threadIdx.x;
    const int wid = tid >> 5, lane = tid & 31;
    const int bm = blockIdx.y * 128, bn = blockIdx.x * 128;
    const int wm = (wid & 3) * 32, wn = (wid >> 2) * 64;
    const int tq = lane >> 2, tr = lane & 3;

    float c[2][8][4];
#pragma unroll
    for (int mf = 0; mf < 2; mf++)
#pragma unroll
        for (int nf = 0; nf < 8; nf++)
#pragma unroll
            for (int r = 0; r < 4; r++) c[mf][nf][r] = 0.0f;

    for (int kc = 0; kc < K; kc += 64) {
#pragma unroll
        for (int it = 0; it < 4; it++) {
            int idx = tid + it * 256;
            int r = idx >> 3, g = idx & 7;
            int doff = r * GS + g * 8;
            if (SPLITA) {
                const float *ap = (const float *)Aq + (size_t)(bm + r) * K + kc + g * 8;
                float4 v0 = *(const float4 *)ap;
                float4 v1 = *(const float4 *)(ap + 4);
                bf16 h[8], l[8];
                split2(v0.x, h[0], l[0]); split2(v0.y, h[1], l[1]);
                split2(v0.z, h[2], l[2]); split2(v0.w, h[3], l[3]);
                split2(v1.x, h[4], l[4]); split2(v1.y, h[5], l[5]);
                split2(v1.z, h[6], l[6]); split2(v1.w, h[7], l[7]);
                *(uint4 *)(sAh + doff) = make_uint4(pkbf(h[0], h[1]), pkbf(h[2], h[3]),
                                                    pkbf(h[4], h[5]), pkbf(h[6], h[7]));
                *(uint4 *)(sAl + doff) = make_uint4(pkbf(l[0], l[1]), pkbf(l[2], l[3]),
                                                    pkbf(l[4], l[5]), pkbf(l[6], l[7]));
            } else {
                size_t aoff = (size_t)(bm + r) * K + kc + g * 8;
                *(uint4 *)(sAh + doff) = *(const uint4 *)((const bf16 *)Aq + aoff);
                *(uint4 *)(sAl + doff) = *(const uint4 *)(Albf + aoff);
            }
            size_t boff = (size_t)(bn + r) * K + kc + g * 8;
            *(uint4 *)(sBh + doff) = *(const uint4 *)(Bh + boff);
            *(uint4 *)(sBl + doff) = *(const uint4 *)(Bl + boff);
        }
        __syncthreads();
#pragma unroll
        for (int ks = 0; ks < 4; ks++) {
            int k0 = ks * 16;
            uint32_t ah[2][4], al[2][4];
#pragma unroll
            for (int mf = 0; mf < 2; mf++) {
                int base = (wm + mf * 16 + tq) * GS + k0 + tr * 2;
                ah[mf][0] = *(const uint32_t *)(sAh + base);
                ah[mf][1] = *(const uint32_t *)(sAh + base + 8 * GS);
                ah[mf][2] = *(const uint32_t *)(sAh + base + 8);
                ah[mf][3] = *(const uint32_t *)(sAh + base + 8 * GS + 8);
                al[mf][0] = *(const uint32_t *)(sAl + base);
                al[mf][1] = *(const uint32_t *)(sAl + base + 8 * GS);
                al[mf][2] = *(const uint32_t *)(sAl + base + 8);
                al[mf][3] = *(const uint32_t *)(sAl + base + 8 * GS + 8);
            }
#pragma unroll
            for (int nf = 0; nf < 8; nf++) {
                int bbase = (wn + nf * 8 + tq) * GS + k0 + tr * 2;
                uint32_t bh0 = *(const uint32_t *)(sBh + bbase);
                uint32_t bh1 = *(const uint32_t *)(sBh + bbase + 8);
                uint32_t bl0 = *(const uint32_t *)(sBl + bbase);
                uint32_t bl1 = *(const uint32_t *)(sBl + bbase + 8);
#pragma unroll
                for (int mf = 0; mf < 2; mf++) {
                    mma_bf16(c[mf][nf], ah[mf], bh0, bh1);
                    mma_bf16(c[mf][nf], ah[mf], bl0, bl1);
                    mma_bf16(c[mf][nf], al[mf], bh0, bh1);
                }
            }
        }
        __syncthreads();
    }
    // fp16 epilogue
#pragma unroll
    for (int mf = 0; mf < 2; mf++)
#pragma unroll
        for (int half_ = 0; half_ < 2; half_++) {
            int row = bm + wm + mf * 16 + tq + half_ * 8;
            __half *rp = C + (size_t)row * N + bn + wn + tr * 2;
#pragma unroll
            for (int nf = 0; nf < 8; nf++) {
                __half2 hv = __float22half2_rn(
                    make_float2(c[mf][nf][2 * half_], c[mf][nf][2 * half_ + 1]));
                *(__half2 *)(rp + nf * 8) = hv;
            }
        }
}

// ---------------- gather layer 1 (fp16 pre, lane = 8 consecutive feats) ------
__global__ void k_gather1(const __half *__restrict__ pre, bf16 *__restrict__ hh,
                          bf16 *__restrict__ hl, const int *__restrict__ rowp,
                          const int *__restrict__ col, const float *__restrict__ dinv,
                          const float *__restrict__ bias, int n) {
    int warp = (blockIdx.x * blockDim.x + threadIdx.x) >> 5;
    int lane = threadIdx.x & 31;
    if (warp >= n) return;
    const uint4 *p4 = (const uint4 *)pre;     // 32 uint4 per node row (256 halves)
    float dn = dinv[warp];
    float nn = dn * dn;

    float a[8];
    {
        uint4 v = p4[(size_t)warp * 32 + lane];
        const __half2 *hp = (const __half2 *)&v;
#pragma unroll
        for (int j = 0; j < 4; j++) {
            float2 f = __half22float2(hp[j]);
            a[2 * j] = f.x * nn; a[2 * j + 1] = f.y * nn;
        }
    }

    int s0 = rowp[warp], s1 = rowp[warp + 1];
    for (int base = s0; base < s1; base += 32) {
        int m = s1 - base; if (m > 32) m = 32;
        int srcv = 0; float nrmv = 0.0f;
        if (lane < m) { srcv = col[base + lane]; nrmv = dinv[srcv] * dn; }
        for (int j = 0; j < m; j++) {
            int s = __shfl_sync(0xffffffffu, srcv, j);
            float w = __shfl_sync(0xffffffffu, nrmv, j);
            uint4 v = p4[(size_t)s * 32 + lane];
            const __half2 *hp = (const __half2 *)&v;
#pragma unroll
            for (int q = 0; q < 4; q++) {
                float2 f = __half22float2(hp[q]);
                a[2 * q] += f.x * w; a[2 * q + 1] += f.y * w;
            }
        }
    }
    float4 b0 = *(const float4 *)(bias + lane * 8);
    float4 b1 = *(const float4 *)(bias + lane * 8 + 4);
    float f[8];
    f[0] = fmaxf(a[0] + b0.x, 0.f); f[1] = fmaxf(a[1] + b0.y, 0.f);
    f[2] = fmaxf(a[2] + b0.z, 0.f); f[3] = fmaxf(a[3] + b0.w, 0.f);
    f[4] = fmaxf(a[4] + b1.x, 0.f); f[5] = fmaxf(a[5] + b1.y, 0.f);
    f[6] = fmaxf(a[6] + b1.z, 0.f); f[7] = fmaxf(a[7] + b1.w, 0.f);
    bf16 h[8], l[8];
#pragma unroll
    for (int j = 0; j < 8; j++) split2(f[j], h[j], l[j]);
    ((uint4 *)hh)[(size_t)warp * 32 + lane] =
        make_uint4(pkbf(h[0], h[1]), pkbf(h[2], h[3]), pkbf(h[4], h[5]), pkbf(h[6], h[7]));
    ((uint4 *)hl)[(size_t)warp * 32 + lane] =
        make_uint4(pkbf(l[0], l[1]), pkbf(l[2], l[3]), pkbf(l[4], l[5]), pkbf(l[6], l[7]));
}

// ---------------- gather layer 2 + reparametrize (fp16 pre) -------------------
__global__ void k_gather2(const __half *__restrict__ pre, const int *__restrict__ rowp,
                          const int *__restrict__ col, const float *__restrict__ dinv,
                          const float *__restrict__ bmu, const float *__restrict__ bls,
                          const float *__restrict__ eps, float *__restrict__ z,
                          float *__restrict__ out,
                          int n, size_t mu_off, size_t ls_off) {
    int warp = (blockIdx.x * blockDim.x + threadIdx.x) >> 5;
    int lane = threadIdx.x & 31;
    if (warp >= n) return;
    const uint4 *p4 = (const uint4 *)pre;
    float dn = dinv[warp];
    float nn = dn * dn;

    float a[8];
    {
        uint4 v = p4[(size_t)warp * 32 + lane];
        const __half2 *hp = (const __half2 *)&v;
#pragma unroll
        for (int j = 0; j < 4; j++) {
            float2 f = __half22float2(hp[j]);
            a[2 * j] = f.x * nn; a[2 * j + 1] = f.y * nn;
        }
    }

    int s0 = rowp[warp], s1 = rowp[warp + 1];
    for (int base = s0; base < s1; base += 32) {
        int m = s1 - base; if (m > 32) m = 32;
        int srcv = 0; float nrmv = 0.0f;
        if (lane < m) { srcv = col[base + lane]; nrmv = dinv[srcv] * dn; }
        for (int j = 0; j < m; j++) {
            int s = __shfl_sync(0xffffffffu, srcv, j);
            float w = __shfl_sync(0xffffffffu, nrmv, j);
            uint4 v = p4[(size_t)s * 32 + lane];
            const __half2 *hp = (const __half2 *)&v;
#pragma unroll
            for (int q = 0; q < 4; q++) {
                float2 f = __half22float2(hp[q]);
                a[2 * q] += f.x * w; a[2 * q + 1] += f.y * w;
            }
        }
    }
    // lanes 0-15: mu features lane*8..+8; lanes 16-31: logstd (lane-16)*8..+8
    float val[8];
    if (lane < 16) {
        float4 b0 = *(const float4 *)(bmu + lane * 8);
        float4 b1 = *(const float4 *)(bmu + lane * 8 + 4);
        val[0] = a[0] + b0.x; val[1] = a[1] + b0.y; val[2] = a[2] + b0.z; val[3] = a[3] + b0.w;
        val[4] = a[4] + b1.x; val[5] = a[5] + b1.y; val[6] = a[6] + b1.z; val[7] = a[7] + b1.w;
    } else {
        float4 b0 = *(const float4 *)(bls + (lane - 16) * 8);
        float4 b1 = *(const float4 *)(bls + (lane - 16) * 8 + 4);
        val[0] = a[0] + b0.x; val[1] = a[1] + b0.y; val[2] = a[2] + b0.z; val[3] = a[3] + b0.w;
        val[4] = a[4] + b1.x; val[5] = a[5] + b1.y; val[6] = a[6] + b1.z; val[7] = a[7] + b1.w;
    }
    // exchange: lane<16 fetches ls from lane+16
    float ls[8];
#pragma unroll
    for (int j = 0; j < 8; j++)
        ls[j] = __shfl_sync(0xffffffffu, val[j], (lane + 16) & 31);

    if (lane < 16) {
        size_t fo = (size_t)warp * LAT + lane * 8;
        float4 e0 = *(const float4 *)(eps + fo);
        float4 e1 = *(const float4 *)(eps + fo + 4);
        float4 z0, z1;
        z0.x = e0.x * __expf(ls[0]) + val[0];
        z0.y = e0.y * __expf(ls[1]) + val[1];
        z0.z = e0.z * __expf(ls[2]) + val[2];
        z0.w = e0.w * __expf(ls[3]) + val[3];
        z1.x = e1.x * __expf(ls[4]) + val[4];
        z1.y = e1.y * __expf(ls[5]) + val[5];
        z1.z = e1.z * __expf(ls[6]) + val[6];
        z1.w = e1.w * __expf(ls[7]) + val[7];
        *(float4 *)(z + fo) = z0;
        *(float4 *)(z + fo + 4) = z1;
        *(float4 *)(out + mu_off + fo) =
            make_float4(val[0], val[1], val[2], val[3]);
        *(float4 *)(out + mu_off + fo + 4) =
            make_float4(val[4], val[5], val[6], val[7]);
    } else {
        size_t fo = (size_t)warp * LAT + (lane - 16) * 8;
        *(float4 *)(out + ls_off + fo) =
            make_float4(val[0], val[1], val[2], val[3]);
        *(float4 *)(out + ls_off + fo + 4) =
            make_float4(val[4], val[5], val[6], val[7]);
    }
}

// ---------------- adj = sigmoid(Z Z^T), TF32 single-term, K 2-chunk ----------
#define ZS4 68
#define ZTILE4 (128 * ZS4)
#define ZT_SMEM (2 * ZTILE4 * 4)

__global__ __launch_bounds__(256, 2)
void k_zzt_tf32(const float *__restrict__ z, float *__restrict__ out, int n) {
    extern __shared__ char smem[];
    uint32_t *sA = (uint32_t *)smem;
    uint32_t *sB = sA + ZTILE4;

    int i = blockIdx.x;
    int bx = (int)((sqrtf(8.0f * (float)i + 1.0f) - 1.0f) * 0.5f);
    while ((bx + 1) * (bx + 2) / 2 <= i) bx++;
    while (bx * (bx + 1) / 2 > i) bx--;
    int by = i - bx * (bx + 1) / 2;
    const int bm = by * 128, bn = bx * 128;

    const int tid = threadIdx.x;
    const int wid = tid >> 5, lane = tid & 31;
    const int wm = (wid & 3) * 32, wn = (wid >> 2) * 64;
    const int tq = lane >> 2, tr = lane & 3;

    float c[2][8][4];
#pragma unroll
    for (int mf = 0; mf < 2; mf++)
#pragma unroll
        for (int nf = 0; nf < 8; nf++)
#pragma unroll
            for (int r = 0; r < 4; r++) c[mf][nf][r] = 0.0f;

#pragma unroll
    for (int kc = 0; kc < LAT; kc += 64) {
        if (kc) __syncthreads();
#pragma unroll
        for (int it = 0; it < 8; it++) {
            int idx = tid + it * 256;
            int r = idx >> 4, g = idx & 15;
            float4 va = *(const float4 *)(z + (size_t)(bm + r) * LAT + kc + g * 4);
            float4 vb = *(const float4 *)(z + (size_t)(bn + r) * LAT + kc + g * 4);
            int doff = r * ZS4 + g * 4;
            sA[doff + 0] = to_tf32(va.x); sA[doff + 1] = to_tf32(va.y);
            sA[doff + 2] = to_tf32(va.z); sA[doff + 3] = to_tf32(va.w);
            sB[doff + 0] = to_tf32(vb.x); sB[doff + 1] = to_tf32(vb.y);
            sB[doff + 2] = to_tf32(vb.z); sB[doff + 3] = to_tf32(vb.w);
        }
        __syncthreads();
#pragma unroll
        for (int ks = 0; ks < 8; ks++) {
            int k0 = ks * 8;
            uint32_t a[2][4];
#pragma unroll
            for (int mf = 0; mf < 2; mf++) {
                int base = (wm + mf * 16 + tq) * ZS4 + k0 + tr;
                a[mf][0] = sA[base];
                a[mf][1] = sA[base + 8 * ZS4];
                a[mf][2] = sA[base + 4];
                a[mf][3] = sA[base + 8 * ZS4 + 4];
            }
#pragma unroll
            for (int nf = 0; nf < 8; nf++) {
                int bbase = (wn + nf * 8 + tq) * ZS4 + k0 + tr;
                uint32_t b0 = sB[bbase];
                uint32_t b1 = sB[bbase + 4];
#pragma unroll
                for (int mf = 0; mf < 2; mf++)
                    mma_tf32(c[mf][nf], a[mf], b0, b1);
            }
        }
    }

#pragma unroll
    for (int mf = 0; mf < 2; mf++)
#pragma unroll
        for (int nf = 0; nf < 8; nf++)
#pragma unroll
            for (int r = 0; r < 4; r++)
                c[mf][nf][r] = fast_sigmoid(c[mf][nf][r]);

#pragma unroll
    for (int mf = 0; mf < 2; mf++)
#pragma unroll
        for (int half_ = 0; half_ < 2; half_++) {
            int row = bm + wm + mf * 16 + tq + half_ * 8;
            float *rp = out + (size_t)row * n + bn + wn + tr * 2;
#pragma unroll
            for (int nf = 0; nf < 8; nf++)
                *(float2 *)(rp + nf * 8) =
                    make_float2(c[mf][nf][2 * half_], c[mf][nf][2 * half_ + 1]);
        }

    if (bx == by) return;

    __syncthreads();
    float *sT = (float *)smem;
#pragma unroll
    for (int mf = 0; mf < 2; mf++)
#pragma unroll
        for (int nf = 0; nf < 8; nf++) {
            int colc = wn + nf * 8 + tr * 2;
            int row0 = wm + mf * 16 + tq;
            sT[(colc + 0) * 132 + row0]     = c[mf][nf][0];
            sT[(colc + 1) * 132 + row0]     = c[mf][nf][1];
            sT[(colc + 0) * 132 + row0 + 8] = c[mf][nf][2];
            sT[(colc + 1) * 132 + row0 + 8] = c[mf][nf][3];
        }
    __syncthreads();
#pragma unroll
    for (int it = 0; it < 16; it++) {
        int idx = tid + it * 256;
        int mr = idx >> 5, mc4 = idx & 31;
        float4 v = *(const float4 *)&sT[mr * 132 + mc4 * 4];
        *(float4 *)(out + (size_t)(bn + mr) * n + bm + mc4 * 4) = v;
    }
}

// ---------------- launcher ----------------
extern "C" void kernel_launch(void *const *d_in, const int *in_sizes, int n_in,
                              void *d_out, int out_size) {
    const float *x   = (const float *)d_in[0];
    const int *ei    = (const int *)d_in[1];
    const float *eps = (const float *)d_in[2];
    const float *W1  = (const float *)d_in[3];
    const float *b1  = (const float *)d_in[4];
    const float *Wmu = (const float *)d_in[5];
    const float *bmu = (const float *)d_in[6];
    const float *Wls = (const float *)d_in[7];
    const float *bls = (const float *)d_in[8];
    float *out       = (float *)d_out;

    const int n = in_sizes[0] / IN_DIM;   // 8192
    const int E = in_sizes[1] / 2;        // 262144
    const int *src = ei;
    const int *dst = ei + E;

    float *dinv, *zbuf;
    __half *pre1, *pre3;
    bf16 *hh, *hl, *w1h, *w1l, *w23h, *w23l;
    int *cnt, *rowp, *priv, *col;
    cudaGetSymbolAddress((void **)&pre1, g_pre1);
    cudaGetSymbolAddress((void **)&pre3, g_pre3);
    cudaGetSymbolAddress((void **)&dinv, g_dinv);
    cudaGetSymbolAddress((void **)&zbuf, g_z);
    cudaGetSymbolAddress((void **)&cnt,  g_cnt);
    cudaGetSymbolAddress((void **)&rowp, g_rowp);
    cudaGetSymbolAddress((void **)&priv, g_priv);
    cudaGetSymbolAddress((void **)&col,  g_col);
    cudaGetSymbolAddress((void **)&hh,   g_hh);
    cudaGetSymbolAddress((void **)&hl,   g_hl);
    cudaGetSymbolAddress((void **)&w1h,  g_w1t_h);
    cudaGetSymbolAddress((void **)&w1l,  g_w1t_l);
    cudaGetSymbolAddress((void **)&w23h, g_w23t_h);
    cudaGetSymbolAddress((void **)&w23l, g_w23t_l);

    static int smem_set = 0;
    if (!smem_set) {
        cudaFuncSetAttribute(k_zzt_tf32, cudaFuncAttributeMaxDynamicSharedMemorySize,
                             ZT_SMEM);
        cudaFuncSetAttribute(k_gemm_bs<0>, cudaFuncAttributeMaxDynamicSharedMemorySize,
                             GSMEM);
        cudaFuncSetAttribute(k_gemm_bs<1>, cudaFuncAttributeMaxDynamicSharedMemorySize,
                             GSMEM);
        smem_set = 1;
    }

    const size_t mu_off = (size_t)n * n;
    const size_t ls_off = mu_off + (size_t)n * LAT;

    // ---- fork: CSR build on side stream ----
    cudaEventRecord(g_side.evFork, 0);
    cudaStreamWaitEvent(g_side.side, g_side.evFork, 0);

    cudaMemsetAsync(priv, 0, NNODE * NCHUNK * sizeof(int), g_side.side);
    k_hist_priv<<<(E + 255) / 256, 256, 0, g_side.side>>>(priv, dst, E);
    k_sum<<<(n * 32 + 255) / 256, 256, 0, g_side.side>>>(priv, cnt, n);
    k_scan<<<1, 1024, 0, g_side.side>>>(cnt, rowp, dinv);
    k_offsets<<<(n * 32 + 255) / 256, 256, 0, g_side.side>>>(priv, rowp, n);
    k_fill_priv<<<(E + 255) / 256, 256, 0, g_side.side>>>(priv, col, src, dst, E);
    cudaEventRecord(g_side.evJoin, g_side.side);

    // ---- main stream: weight conversion + GEMM1 (x split fused in-kernel) ----
    int wthreads = IN_DIM * HID + F2 * HID;
    k_convert_w<<<(wthreads + 255) / 256, 256>>>(W1, Wmu, Wls, w1h, w1l, w23h, w23l);
    k_gemm_bs<1><<<dim3(HID / 128, n / 128), 256, GSMEM>>>(x, nullptr, w1h, w1l,
                                                           pre1, n, HID, IN_DIM);

    // ---- join: gathers need CSR ----
    cudaStreamWaitEvent(0, g_side.evJoin, 0);

    k_gather1<<<(n * 32 + 255) / 256, 256>>>(pre1, hh, hl, rowp, col, dinv, b1, n);
    k_gemm_bs<0><<<dim3(F2 / 128, n / 128), 256, GSMEM>>>(hh, hl, w23h, w23l, pre3,
                                                          n, F2, HID);
    k_gather2<<<(n * 32 + 255) / 256, 256>>>(pre3, rowp, col, dinv, bmu, bls, eps,
                                             zbuf, out, n, mu_off, ls_off);

    int nt = (n / 128) * (n / 128 + 1) / 2;   // 2080
    k_zzt_tf32<<<nt, 256, ZT_SMEM>>>(zbuf, out, n);
}